// round 7
// baseline (speedup 1.0000x reference)
#include <cuda_runtime.h>
#include <cuda_bf16.h>
#include <math.h>
#include <stdint.h>

#define B 8
#define SEQ 2048
#define HID 512
#define HD 64

// ---------------- scratch (device globals; no allocation allowed) ----------------
__device__ __align__(256) uint16_t gQh[B * SEQ * HD], gQl[B * SEQ * HD];
__device__ __align__(256) uint16_t gKh[B * SEQ * HD], gKl[B * SEQ * HD];
__device__ __align__(256) uint16_t gVh[B * SEQ * HD], gVl[B * SEQ * HD];
__device__ __align__(256) uint16_t gWh[192 * HID], gWl[192 * HID];   // [region*64+d][k]
__device__ __align__(256) float gC[B * 8 * HD * HD];   // chunk KV states, fp32
__device__ float tQc[SEQ * 32], tQs[SEQ * 32], tKc[SEQ * 32], tKs[SEQ * 32];
__device__ float tDec[4096];   // gamma^|d|, index d+2048

// ---------------- helpers ----------------
__device__ __forceinline__ void mma_bf16(float* d, const uint32_t* a, const uint32_t* b) {
    asm volatile(
        "mma.sync.aligned.m16n8k16.row.col.f32.bf16.bf16.f32 "
        "{%0,%1,%2,%3}, {%4,%5,%6,%7}, {%8,%9}, {%0,%1,%2,%3};"
        : "+f"(d[0]), "+f"(d[1]), "+f"(d[2]), "+f"(d[3])
        : "r"(a[0]), "r"(a[1]), "r"(a[2]), "r"(a[3]), "r"(b[0]), "r"(b[1]));
}
#define LDM_X4(R, a) \
    asm volatile("ldmatrix.sync.aligned.m8n8.x4.shared.b16 {%0,%1,%2,%3}, [%4];" \
                 : "=r"((R)[0]), "=r"((R)[1]), "=r"((R)[2]), "=r"((R)[3]) : "r"(a))
#define LDM_X4T(R, a) \
    asm volatile("ldmatrix.sync.aligned.m8n8.x4.trans.shared.b16 {%0,%1,%2,%3}, [%4];" \
                 : "=r"((R)[0]), "=r"((R)[1]), "=r"((R)[2]), "=r"((R)[3]) : "r"(a))
#define CPA16(dst, src) \
    asm volatile("cp.async.ca.shared.global [%0], [%1], 16;" \
                 :: "r"(dst), "l"(__cvta_generic_to_global(src)))
#define CPA_COMMIT() asm volatile("cp.async.commit_group;")
#define CPA_WAIT1() asm volatile("cp.async.wait_group 1;")
#define CPA_WAIT0() asm volatile("cp.async.wait_group 0;")
__device__ __forceinline__ uint32_t smem_u32(const void* p) {
    uint32_t a;
    asm("{ .reg .u64 t; cvta.to.shared.u64 t, %1; cvt.u32.u64 %0, t; }" : "=r"(a) : "l"(p));
    return a;
}
__device__ __forceinline__ uint32_t pack_bf(float x0, float x1) {
    uint32_t r;
    asm("cvt.rn.bf16x2.f32 %0, %1, %2;" : "=r"(r) : "f"(x1), "f"(x0));
    return r;
}
// hi = truncated bf16 pair (PRMT), lo = RN(residual) pair; hi+lo ~ 2^-17 rel.
__device__ __forceinline__ uint32_t split_pair(float x0, float x1, uint32_t& lo) {
    uint32_t u0 = __float_as_uint(x0) & 0xFFFF0000u;
    uint32_t u1 = __float_as_uint(x1) & 0xFFFF0000u;
    uint32_t hi = __byte_perm(u0, u1, 0x7632);
    float l0 = x0 - __uint_as_float(u0);
    float l1 = x1 - __uint_as_float(u1);
    lo = pack_bf(l0, l1);
    return hi;
}
// unpack packed bf16x2 pair to floats
__device__ __forceinline__ void unpack_bf2(uint32_t p, float& x0, float& x1) {
    x0 = __uint_as_float(p << 16);
    x1 = __uint_as_float(p & 0xFFFF0000u);
}

// ---------------- kernel 0: tables + W split (full-width parallel) ----------------
__global__ void prep_kernel(const float* __restrict__ WQ,
                            const float* __restrict__ WK,
                            const float* __restrict__ WV) {
    int idx = blockIdx.x * blockDim.x + threadIdx.x;
    if (idx < 4096) {
        float d = fabsf((float)(idx - 2048));
        tDec[idx] = exp2f(log2f(0.96875f) * d);
    }
    if (idx < SEQ * 32) {
        int t = idx >> 5;
        int m = idx & 31;
        float sv = (2.0f * (float)m + 0.4f * (float)HD) / (1.4f * (float)HD);
        float p = ((float)t * (1.0f / 512.0f)) * log2f(sv);
        float s = exp2f(p);
        float rs = exp2f(-p);
        // angle-critical: keep powf (matches measured baseline)
        float invf = 1.0f / powf(10000.0f, (float)m / 32.0f);
        float sn, cs;
        sincosf((float)t * invf, &sn, &cs);
        tQc[idx] = cs * s;
        tQs[idx] = sn * s;
        tKc[idx] = cs * rs;
        tKs[idx] = sn * rs;
    }
    if (idx < 3 * HID * HD) {
        int region = idx >> 15;
        int k = (idx & 32767) >> 6;
        int d = idx & 63;
        const float* W = (region == 0) ? WQ : ((region == 1) ? WK : WV);
        float w = W[k * HD + d];
        __nv_bfloat16 hb = __float2bfloat16(w);
        gWh[(region * 64 + d) * HID + k] = __bfloat16_as_ushort(hb);
        gWl[(region * 64 + d) * HID + k] =
            __bfloat16_as_ushort(__float2bfloat16(w - __bfloat162float(hb)));
    }
}

// ---------------- kernel 1: QKV projection via HMMA + xPos (cp.async pipelined) ----------------
#define PSTR 72
#define PX(s)   ((s) * 32768)
#define P_BH(s) (65536 + (s) * 55296)
#define P_BL(s) (65536 + (s) * 55296 + 27648)
#define P_AH 176128
#define P_AL 194560
#define P_TOTAL 212992

__device__ __forceinline__ void proj_prefetch(uint32_t smb, const float* Xb, int k0,
                                              int s, int tid) {
#pragma unroll
    for (int it = 0; it < 8; it++) {
        int e = tid + it * 256;
        int r = e >> 4, c = e & 15;
        CPA16(smb + PX(s) + r * 256 + c * 16, &Xb[r * HID + k0 + c * 4]);
    }
#pragma unroll
    for (int it = 0; it < 6; it++) {
        int e = tid + it * 256;
        int r = e >> 3, c = e & 7;
        CPA16(smb + P_BH(s) + r * 144 + c * 16, &gWh[r * HID + k0 + c * 8]);
        CPA16(smb + P_BL(s) + r * 144 + c * 16, &gWl[r * HID + k0 + c * 8]);
    }
}

__global__ __launch_bounds__(256, 1) void proj_kernel(const float* __restrict__ X) {
    extern __shared__ char sm[];
    uint16_t* Ah = (uint16_t*)(sm + P_AH);
    uint16_t* Al = (uint16_t*)(sm + P_AL);
    uint32_t smb = smem_u32(sm);

    int tid = threadIdx.x;
    int wid = tid >> 5, lane = tid & 31;
    int wm = wid >> 1, wn = wid & 1;
    int g = lane >> 2, tc = lane & 3;

    int arow = lane & 15;
    int acolb = (lane >> 4) * 16;
    int krow = (lane & 7) + ((lane >> 4) << 3);
    int kcolb = ((lane >> 3) & 1) * 16;

    const float* Xb = X + (size_t)blockIdx.x * 128 * HID;

    float acc[2][12][4];
#pragma unroll
    for (int mt = 0; mt < 2; mt++)
#pragma unroll
        for (int nt = 0; nt < 12; nt++)
#pragma unroll
            for (int i = 0; i < 4; i++) acc[mt][nt][i] = 0.0f;

    proj_prefetch(smb, Xb, 0, 0, tid);
    CPA_COMMIT();

    for (int chunk = 0; chunk < 8; chunk++) {
        int s = chunk & 1;
        if (chunk < 7) {
            proj_prefetch(smb, Xb, (chunk + 1) * 64, s ^ 1, tid);
            CPA_COMMIT();
            CPA_WAIT1();
        } else {
            CPA_WAIT0();
        }
        __syncthreads();

        {
            const float* Xs = (const float*)(sm + PX(s));
#pragma unroll
            for (int it = 0; it < 8; it++) {
                int e = tid + it * 256;
                int r = e >> 4, q = e & 15;
                float4 v = *(const float4*)&Xs[r * 64 + q * 4];
                uint32_t lo0, lo1;
                uint32_t h0 = split_pair(v.x, v.y, lo0);
                uint32_t h1 = split_pair(v.z, v.w, lo1);
                *(uint2*)&Ah[r * PSTR + 4 * q] = make_uint2(h0, h1);
                *(uint2*)&Al[r * PSTR + 4 * q] = make_uint2(lo0, lo1);
            }
        }
        __syncthreads();

        uint32_t bhBase = smb + P_BH(s);
        uint32_t blBase = smb + P_BL(s);
#pragma unroll
        for (int ks = 0; ks < 4; ks++) {
            uint32_t ah[2][4], al[2][4];
#pragma unroll
            for (int mt = 0; mt < 2; mt++) {
                uint32_t rb = (uint32_t)((wm * 32 + mt * 16 + arow) * (PSTR * 2) + ks * 32 + acolb);
                LDM_X4(ah[mt], smb + P_AH + rb);
                LDM_X4(al[mt], smb + P_AL + rb);
            }
#pragma unroll
            for (int np = 0; np < 6; np++) {
                int n = wn * 96 + np * 16;
                uint32_t bb = (uint32_t)((n + krow) * (PSTR * 2) + ks * 32 + kcolb);
                uint32_t bh[4], bl[4];
                LDM_X4(bh, bhBase + bb);
                LDM_X4(bl, blBase + bb);
#pragma unroll
                for (int mt = 0; mt < 2; mt++) {
                    mma_bf16(acc[mt][2 * np], ah[mt], &bh[0]);
                    mma_bf16(acc[mt][2 * np], ah[mt], &bl[0]);
                    mma_bf16(acc[mt][2 * np], al[mt], &bh[0]);
                    mma_bf16(acc[mt][2 * np + 1], ah[mt], &bh[2]);
                    mma_bf16(acc[mt][2 * np + 1], ah[mt], &bl[2]);
                    mma_bf16(acc[mt][2 * np + 1], al[mt], &bh[2]);
                }
            }
        }
        __syncthreads();
    }

#pragma unroll
    for (int mt = 0; mt < 2; mt++) {
#pragma unroll
        for (int half = 0; half < 2; half++) {
            int lrow = wm * 32 + mt * 16 + g + half * 8;
            int grow = blockIdx.x * 128 + lrow;
            int tpos = grow & (SEQ - 1);
#pragma unroll
            for (int nt = 0; nt < 12; nt++) {
                int c = wn * 96 + nt * 8 + 2 * tc;
                float v0 = acc[mt][nt][half * 2];
                float v1 = acc[mt][nt][half * 2 + 1];
                if (c < 64) {
                    int m = c >> 1;
                    float cs = tQc[tpos * 32 + m], sn = tQs[tpos * 32 + m];
                    float o0 = v0 * cs - v1 * sn;
                    float o1 = v1 * cs + v0 * sn;
                    uint32_t lo;
                    uint32_t hi = split_pair(o0, o1, lo);
                    ((uint32_t*)gQh)[grow * 32 + m] = hi;
                    ((uint32_t*)gQl)[grow * 32 + m] = lo;
                } else if (c < 128) {
                    int m = (c - 64) >> 1;
                    float cs = tKc[tpos * 32 + m], sn = tKs[tpos * 32 + m];
                    float o0 = v0 * cs - v1 * sn;
                    float o1 = v1 * cs + v0 * sn;
                    uint32_t lo;
                    uint32_t hi = split_pair(o0, o1, lo);
                    ((uint32_t*)gKh)[grow * 32 + m] = hi;
                    ((uint32_t*)gKl)[grow * 32 + m] = lo;
                } else {
                    int m = (c - 128) >> 1;
                    uint32_t lo;
                    uint32_t hi = split_pair(v0, v1, lo);
                    ((uint32_t*)gVh)[grow * 32 + m] = hi;
                    ((uint32_t*)gVl)[grow * 32 + m] = lo;
                }
            }
        }
    }
}

// ---------------- kernel 1.5: chunk KV state C_c = sum_j gamma^(c_end+1-j) K_j^T V_j ----------------
// grid (7 chunks, 8 b) x 128 thr. C_c used by chunks > c. Output fp32 [b][c][d][v].
#define SC_KH 0
#define SC_KL 9216
#define SC_VH 18432
#define SC_VL 27648
#define SC_TOTAL 36864

__global__ __launch_bounds__(128) void state_kernel() {
    extern __shared__ char sm[];
    uint32_t smb = smem_u32(sm);
    int c = blockIdx.x, b = blockIdx.y;
    int tid = threadIdx.x;
    int wid = tid >> 5, lane = tid & 31;
    int g = lane >> 2, tc = lane & 3;

    int arow = lane & 15;
    int acolb = (lane >> 4) * 16;
    int krow = (lane & 7) + ((lane >> 4) << 3);
    int kcolb = ((lane >> 3) & 1) * 16;

    float acc[8][4];
#pragma unroll
    for (int nd = 0; nd < 8; nd++)
#pragma unroll
        for (int i = 0; i < 4; i++) acc[nd][i] = 0.0f;

    for (int jt = 0; jt < 4; jt++) {
        __syncthreads();
        int jb = b * SEQ + c * 256 + jt * 64;
        // K tile copy (hi/lo)
#pragma unroll
        for (int it = 0; it < 4; it++) {
            int e = tid + it * 128;
            int r = e >> 3, cc = e & 7;
            *(float4*)(sm + SC_KH + r * 144 + cc * 16) = *(const float4*)&gKh[(size_t)(jb + r) * HD + cc * 8];
            *(float4*)(sm + SC_KL + r * 144 + cc * 16) = *(const float4*)&gKl[(size_t)(jb + r) * HD + cc * 8];
        }
        // V weighted: w = gamma^(256 - jj)
#pragma unroll
        for (int it = 0; it < 16; it++) {
            int p = tid + it * 128;
            int r = p >> 5, vp = p & 31;
            uint32_t hi = ((const uint32_t*)gVh)[(size_t)(jb + r) * 32 + vp];
            uint32_t lo = ((const uint32_t*)gVl)[(size_t)(jb + r) * 32 + vp];
            float h0, h1, l0, l1;
            unpack_bf2(hi, h0, h1);
            unpack_bf2(lo, l0, l1);
            float w = tDec[2304 - (jt * 64 + r)];
            uint32_t olo;
            uint32_t ohi = split_pair(w * (h0 + l0), w * (h1 + l1), olo);
            *(uint32_t*)(sm + SC_VH + r * 144 + vp * 4) = ohi;
            *(uint32_t*)(sm + SC_VL + r * 144 + vp * 4) = olo;
        }
        __syncthreads();

        // acc[d][v] += K^T(d x j) @ Vw(j x v), 3-term
#pragma unroll
        for (int ks = 0; ks < 4; ks++) {
            uint32_t ab = (uint32_t)((ks * 16 + krow) * 144 + wid * 32 + kcolb);
            uint32_t ah[4], al[4];
            LDM_X4T(ah, smb + SC_KH + ab);
            LDM_X4T(al, smb + SC_KL + ab);
#pragma unroll
            for (int ndp = 0; ndp < 4; ndp++) {
                uint32_t vb = (uint32_t)((ks * 16 + arow) * 144 + ndp * 32 + acolb);
                uint32_t vh[4], vl[4];
                LDM_X4T(vh, smb + SC_VH + vb);
                LDM_X4T(vl, smb + SC_VL + vb);
                mma_bf16(acc[2 * ndp], ah, &vh[0]);
                mma_bf16(acc[2 * ndp], ah, &vl[0]);
                mma_bf16(acc[2 * ndp], al, &vh[0]);
                mma_bf16(acc[2 * ndp + 1], ah, &vh[2]);
                mma_bf16(acc[2 * ndp + 1], ah, &vl[2]);
                mma_bf16(acc[2 * ndp + 1], al, &vh[2]);
            }
        }
    }

    float* Cb = gC + ((size_t)(b * 8 + c)) * 4096;
#pragma unroll
    for (int nd = 0; nd < 8; nd++) {
        int v = nd * 8 + 2 * tc;
        int d0 = wid * 16 + g;
        *(float2*)&Cb[d0 * 64 + v] = make_float2(acc[nd][0], acc[nd][1]);
        *(float2*)&Cb[(d0 + 8) * 64 + v] = make_float2(acc[nd][2], acc[nd][3]);
    }
}

// ---------------- kernel 2: retention attention (intra-chunk tiles + state) ----------------
// grid (32 qt, 8 b) x 128 thr (4 warps). Exactly 4 intra-chunk tiles + state apply.
#define ASTR 72
#define A_QH 0
#define A_QL 9216
#define A_MH 18432
#define A_ML 27648
#define A_ST 36864
#define A_STSZ 36864
#define A_DEC (A_ST + 2 * A_STSZ)            // 110592: decay window, 511 floats
#define A_TOTAL (A_DEC + 511 * 4 + 4)        // 112640

__device__ __forceinline__ void attn_prefetch(uint32_t smb, int st, int kb, bool near_, int tid) {
    uint32_t base = smb + A_ST + st * A_STSZ;
#pragma unroll
    for (int it = 0; it < 4; it++) {
        int e = tid + it * 128;
        int r = e >> 3, c = e & 7;
        uint32_t off = (uint32_t)(r * 144 + c * 16);
        CPA16(base + off, &gKh[(size_t)(kb + r) * HD + c * 8]);
        CPA16(base + 18432 + off, &gVh[(size_t)(kb + r) * HD + c * 8]);
        if (near_) {
            CPA16(base + 9216 + off, &gKl[(size_t)(kb + r) * HD + c * 8]);
            CPA16(base + 27648 + off, &gVl[(size_t)(kb + r) * HD + c * 8]);
        }
    }
}

__global__ __launch_bounds__(128) void attn_kernel(float* __restrict__ out) {
    extern __shared__ char sm[];
    uint16_t* Qh = (uint16_t*)(sm + A_QH);
    uint16_t* Ql = (uint16_t*)(sm + A_QL);
    float* sDec = (float*)(sm + A_DEC);
    uint32_t smb = smem_u32(sm);

    int qt = blockIdx.x, b = blockIdx.y;
    int tid = threadIdx.x;
    int wid = tid >> 5, lane = tid & 31;
    int g = lane >> 2, tc = lane & 3;
    int q0 = qt * 64;
    int gb = b * SEQ + q0;
    int chunk = qt >> 2;
    int c4t = chunk * 4;

    int arow = lane & 15;
    int acolb = (lane >> 4) * 16;
    int krow = (lane & 7) + ((lane >> 4) << 3);
    int kcolb = ((lane >> 3) & 1) * 16;

    // prefetch tile 0 (kt = c4t)
    {
        bool nr = (qt - c4t) <= 2;
        attn_prefetch(smb, 0, b * SEQ + c4t * 64, nr, tid);
        CPA_COMMIT();
    }

    // load Q tile (hi/lo), decay window, state M
#pragma unroll
    for (int it = 0; it < 4; it++) {
        int e = tid + it * 128;
        int r = e >> 3, c = e & 7;
        *(float4*)&Qh[r * ASTR + c * 8] = *(const float4*)&gQh[(gb + r) * HD + c * 8];
        *(float4*)&Ql[r * ASTR + c * 8] = *(const float4*)&gQl[(gb + r) * HD + c * 8];
    }
    for (int d = tid; d < 511; d += 128) sDec[d] = tDec[d + 1793];
    if (chunk >= 1) {
        const float2* C1 = (const float2*)(gC + ((size_t)(b * 8 + chunk - 1)) * 4096);
        const float2* C2 = (chunk >= 2) ? (const float2*)(gC + ((size_t)(b * 8 + chunk - 2)) * 4096) : (const float2*)0;
        const float G256 = 2.952517e-4f;   // gamma^256
#pragma unroll
        for (int it = 0; it < 16; it++) {
            int p = tid + it * 128;
            int d = p >> 5, vp = p & 31;
            float2 v = C1[p];
            if (C2) {
                float2 w = C2[p];
                v.x += G256 * w.x;
                v.y += G256 * w.y;
            }
            uint32_t lo;
            uint32_t hi = split_pair(v.x, v.y, lo);
            *(uint32_t*)(sm + A_MH + d * 144 + vp * 4) = hi;
            *(uint32_t*)(sm + A_ML + d * 144 + vp * 4) = lo;
        }
    }
    __syncthreads();

    // preload Q fragments
    uint32_t qh[4][4], ql[4][4];
#pragma unroll
    for (int ks = 0; ks < 4; ks++) {
        uint32_t rb = (uint32_t)((wid * 16 + arow) * (ASTR * 2) + ks * 32 + acolb);
        LDM_X4(qh[ks], smb + A_QH + rb);
        LDM_X4(ql[ks], smb + A_QL + rb);
    }

    float oa[8][4];
#pragma unroll
    for (int nd = 0; nd < 8; nd++)
#pragma unroll
        for (int i = 0; i < 4; i++) oa[nd][i] = 0.0f;

    int i0 = q0 + wid * 16 + g;

    // ---- state apply: O += gamma^(i-c0) * Q @ M ----
    if (chunk >= 1) {
        float T[8][4];
#pragma unroll
        for (int nd = 0; nd < 8; nd++)
#pragma unroll
            for (int i = 0; i < 4; i++) T[nd][i] = 0.0f;
#pragma unroll
        for (int ks = 0; ks < 4; ks++) {
#pragma unroll
            for (int ndp = 0; ndp < 4; ndp++) {
                uint32_t vb = (uint32_t)((ks * 16 + arow) * 144 + ndp * 32 + acolb);
                uint32_t mh[4], ml[4];
                LDM_X4T(mh, smb + A_MH + vb);
                LDM_X4T(ml, smb + A_ML + vb);
                mma_bf16(T[2 * ndp], qh[ks], &mh[0]);
                mma_bf16(T[2 * ndp], qh[ks], &ml[0]);
                mma_bf16(T[2 * ndp], ql[ks], &mh[0]);
                mma_bf16(T[2 * ndp + 1], qh[ks], &mh[2]);
                mma_bf16(T[2 * ndp + 1], qh[ks], &ml[2]);
                mma_bf16(T[2 * ndp + 1], ql[ks], &mh[2]);
            }
        }
        int c0 = chunk * 256;
        float sc0 = sDec[i0 - c0 + 255];
        float sc1 = sDec[i0 + 8 - c0 + 255];
#pragma unroll
        for (int nd = 0; nd < 8; nd++) {
            oa[nd][0] += sc0 * T[nd][0];
            oa[nd][1] += sc0 * T[nd][1];
            oa[nd][2] += sc1 * T[nd][2];
            oa[nd][3] += sc1 * T[nd][3];
        }
    }

    // ---- 4 intra-chunk tiles ----
    for (int i = 0; i < 4; i++) {
        int kt = c4t + i;
        int s = i & 1;
        int dd = qt - kt;
        bool nr = (dd <= 2) && (dd >= -2);
        if (i < 3) {
            int kt2 = kt + 1;
            int d2 = qt - kt2;
            bool nr2 = (d2 <= 2) && (d2 >= -2);
            attn_prefetch(smb, s ^ 1, b * SEQ + kt2 * 64, nr2, tid);
            CPA_COMMIT();
            CPA_WAIT1();
        } else {
            CPA_WAIT0();
        }
        __syncthreads();

        uint32_t stb = smb + A_ST + s * A_STSZ;
        uint32_t khB = stb, klB = stb + 9216, vhB = stb + 18432, vlB = stb + 27648;

        float sreg[8][4];
#pragma unroll
        for (int nt = 0; nt < 8; nt++)
#pragma unroll
            for (int ii = 0; ii < 4; ii++) sreg[nt][ii] = 0.0f;

        if (nr) {
#pragma unroll
            for (int ks = 0; ks < 4; ks++) {
#pragma unroll
                for (int np = 0; np < 4; np++) {
                    uint32_t bb = (uint32_t)((np * 16 + krow) * (ASTR * 2) + ks * 32 + kcolb);
                    uint32_t kh[4], kl[4];
                    LDM_X4(kh, khB + bb);
                    LDM_X4(kl, klB + bb);
                    mma_bf16(sreg[2 * np], qh[ks], &kh[0]);
                    mma_bf16(sreg[2 * np], qh[ks], &kl[0]);
                    mma_bf16(sreg[2 * np], ql[ks], &kh[0]);
                    mma_bf16(sreg[2 * np + 1], qh[ks], &kh[2]);
                    mma_bf16(sreg[2 * np + 1], qh[ks], &kl[2]);
                    mma_bf16(sreg[2 * np + 1], ql[ks], &kh[2]);
                }
            }
#pragma unroll
            for (int nt = 0; nt < 8; nt++) {
                int base = i0 - (kt * 64 + nt * 8 + 2 * tc) + 255;
                sreg[nt][0] *= sDec[base];
                sreg[nt][1] *= sDec[base - 1];
                sreg[nt][2] *= sDec[base + 8];
                sreg[nt][3] *= sDec[base + 7];
            }
#pragma unroll
            for (int ks2 = 0; ks2 < 4; ks2++) {
                float* s0 = sreg[2 * ks2];
                float* s1 = sreg[2 * ks2 + 1];
                uint32_t ah[4], al[4];
                ah[0] = split_pair(s0[0], s0[1], al[0]);
                ah[1] = split_pair(s0[2], s0[3], al[1]);
                ah[2] = split_pair(s1[0], s1[1], al[2]);
                ah[3] = split_pair(s1[2], s1[3], al[3]);
#pragma unroll
                for (int ndp = 0; ndp < 4; ndp++) {
                    uint32_t vb = (uint32_t)((ks2 * 16 + arow) * (ASTR * 2) + ndp * 32 + acolb);
                    uint32_t vh[4], vl[4];
                    LDM_X4T(vh, vhB + vb);
                    LDM_X4T(vl, vlB + vb);
                    mma_bf16(oa[2 * ndp], ah, &vh[0]);
                    mma_bf16(oa[2 * ndp], ah, &vl[0]);
                    mma_bf16(oa[2 * ndp], al, &vh[0]);
                    mma_bf16(oa[2 * ndp + 1], ah, &vh[2]);
                    mma_bf16(oa[2 * ndp + 1], ah, &vl[2]);
                    mma_bf16(oa[2 * ndp + 1], al, &vh[2]);
                }
            }
        } else {
            // far intra tile (|qt-kt| == 3): decay <= gamma^129 -> 1-term
#pragma unroll
            for (int ks = 0; ks < 4; ks++) {
#pragma unroll
                for (int np = 0; np < 4; np++) {
                    uint32_t bb = (uint32_t)((np * 16 + krow) * (ASTR * 2) + ks * 32 + kcolb);
                    uint32_t kh[4];
                    LDM_X4(kh, khB + bb);
                    mma_bf16(sreg[2 * np], qh[ks], &kh[0]);
                    mma_bf16(sreg[2 * np + 1], qh[ks], &kh[2]);
                }
            }
#pragma unroll
            for (int nt = 0; nt < 8; nt++) {
                int base = i0 - (kt * 64 + nt * 8 + 2 * tc) + 255;
                sreg[nt][0] *= sDec[base];
                sreg[nt][1] *= sDec[base - 1];
                sreg[nt][2] *= sDec[base + 8];
                sreg[nt][3] *= sDec[base + 7];
            }
#pragma unroll
            for (int ks2 = 0; ks2 < 4; ks2++) {
                float* s0 = sreg[2 * ks2];
                float* s1 = sreg[2 * ks2 + 1];
                uint32_t ah[4];
                ah[0] = pack_bf(s0[0], s0[1]);
                ah[1] = pack_bf(s0[2], s0[3]);
                ah[2] = pack_bf(s1[0], s1[1]);
                ah[3] = pack_bf(s1[2], s1[3]);
#pragma unroll
                for (int ndp = 0; ndp < 4; ndp++) {
                    uint32_t vb = (uint32_t)((ks2 * 16 + arow) * (ASTR * 2) + ndp * 32 + acolb);
                    uint32_t vh[4];
                    LDM_X4T(vh, vhB + vb);
                    mma_bf16(oa[2 * ndp], ah, &vh[0]);
                    mma_bf16(oa[2 * ndp + 1], ah, &vh[2]);
                }
            }
        }
        __syncthreads();
    }

    // store O
#pragma unroll
    for (int nd = 0; nd < 8; nd++) {
        int c = nd * 8 + 2 * tc;
        int r0 = wid * 16 + g;
        *(float2*)&out[(size_t)(gb + r0) * HD + c] = make_float2(oa[nd][0], oa[nd][1]);
        *(float2*)&out[(size_t)(gb + r0 + 8) * HD + c] = make_float2(oa[nd][2], oa[nd][3]);
    }
}

// ---------------- launch ----------------
extern "C" void kernel_launch(void* const* d_in, const int* in_sizes, int n_in,
                              void* d_out, int out_size) {
    const float* X  = (const float*)d_in[0];
    const float* WQ = (const float*)d_in[1];
    const float* WK = (const float*)d_in[2];
    const float* WV = (const float*)d_in[3];
    float* out = (float*)d_out;

    prep_kernel<<<384, 256>>>(WQ, WK, WV);

    cudaFuncSetAttribute(proj_kernel, cudaFuncAttributeMaxDynamicSharedMemorySize, P_TOTAL);
    proj_kernel<<<128, 256, P_TOTAL>>>(X);

    cudaFuncSetAttribute(state_kernel, cudaFuncAttributeMaxDynamicSharedMemorySize, SC_TOTAL);
    state_kernel<<<dim3(7, B), 128, SC_TOTAL>>>();

    cudaFuncSetAttribute(attn_kernel, cudaFuncAttributeMaxDynamicSharedMemorySize, A_TOTAL);
    attn_kernel<<<dim3(32, B), 128, A_TOTAL>>>(out);
}

// round 8
// speedup vs baseline: 1.3781x; 1.3781x over previous
#include <cuda_runtime.h>
#include <cuda_bf16.h>
#include <cuda_fp16.h>
#include <math.h>
#include <stdint.h>

#define B 8
#define SEQ 2048
#define HID 512
#define HD 64

// ---------------- scratch (device globals; no allocation allowed) ----------------
__device__ __align__(256) uint16_t gQh[B * SEQ * HD], gQl[B * SEQ * HD];
__device__ __align__(256) uint16_t gKh[B * SEQ * HD], gKl[B * SEQ * HD];
__device__ __align__(256) uint16_t gVh[B * SEQ * HD], gVl[B * SEQ * HD];
__device__ __align__(256) uint16_t gWf[192 * HID];     // fp16 W, [region*64+d][k]
__device__ __align__(256) float gC[B * 8 * HD * HD];   // chunk KV states, fp32
__device__ float tQc[SEQ * 32], tQs[SEQ * 32], tKc[SEQ * 32], tKs[SEQ * 32];
__device__ float tDec[4096];   // gamma^|d|, index d+2048

// ---------------- helpers ----------------
__device__ __forceinline__ void mma_bf16(float* d, const uint32_t* a, const uint32_t* b) {
    asm volatile(
        "mma.sync.aligned.m16n8k16.row.col.f32.bf16.bf16.f32 "
        "{%0,%1,%2,%3}, {%4,%5,%6,%7}, {%8,%9}, {%0,%1,%2,%3};"
        : "+f"(d[0]), "+f"(d[1]), "+f"(d[2]), "+f"(d[3])
        : "r"(a[0]), "r"(a[1]), "r"(a[2]), "r"(a[3]), "r"(b[0]), "r"(b[1]));
}
__device__ __forceinline__ void mma_f16(float* d, const uint32_t* a, const uint32_t* b) {
    asm volatile(
        "mma.sync.aligned.m16n8k16.row.col.f32.f16.f16.f32 "
        "{%0,%1,%2,%3}, {%4,%5,%6,%7}, {%8,%9}, {%0,%1,%2,%3};"
        : "+f"(d[0]), "+f"(d[1]), "+f"(d[2]), "+f"(d[3])
        : "r"(a[0]), "r"(a[1]), "r"(a[2]), "r"(a[3]), "r"(b[0]), "r"(b[1]));
}
#define LDM_X4(R, a) \
    asm volatile("ldmatrix.sync.aligned.m8n8.x4.shared.b16 {%0,%1,%2,%3}, [%4];" \
                 : "=r"((R)[0]), "=r"((R)[1]), "=r"((R)[2]), "=r"((R)[3]) : "r"(a))
#define LDM_X4T(R, a) \
    asm volatile("ldmatrix.sync.aligned.m8n8.x4.trans.shared.b16 {%0,%1,%2,%3}, [%4];" \
                 : "=r"((R)[0]), "=r"((R)[1]), "=r"((R)[2]), "=r"((R)[3]) : "r"(a))
#define CPA16(dst, src) \
    asm volatile("cp.async.ca.shared.global [%0], [%1], 16;" \
                 :: "r"(dst), "l"(__cvta_generic_to_global(src)))
#define CPA_COMMIT() asm volatile("cp.async.commit_group;")
#define CPA_WAIT1() asm volatile("cp.async.wait_group 1;")
#define CPA_WAIT0() asm volatile("cp.async.wait_group 0;")
__device__ __forceinline__ uint32_t smem_u32(const void* p) {
    uint32_t a;
    asm("{ .reg .u64 t; cvta.to.shared.u64 t, %1; cvt.u32.u64 %0, t; }" : "=r"(a) : "l"(p));
    return a;
}
__device__ __forceinline__ uint32_t pack_bf(float x0, float x1) {
    uint32_t r;
    asm("cvt.rn.bf16x2.f32 %0, %1, %2;" : "=r"(r) : "f"(x1), "f"(x0));
    return r;
}
// bf16 hi = truncated pair (PRMT), lo = RN(residual); hi+lo ~ 2^-17 rel.
__device__ __forceinline__ uint32_t split_pair(float x0, float x1, uint32_t& lo) {
    uint32_t u0 = __float_as_uint(x0) & 0xFFFF0000u;
    uint32_t u1 = __float_as_uint(x1) & 0xFFFF0000u;
    uint32_t hi = __byte_perm(u0, u1, 0x7632);
    float l0 = x0 - __uint_as_float(u0);
    float l1 = x1 - __uint_as_float(u1);
    lo = pack_bf(l0, l1);
    return hi;
}
// fp16 2-term split: hi RN-fp16 pair, lo = RN(residual) pair; hi+lo ~ 2^-23 rel.
__device__ __forceinline__ uint32_t splitf16(float x0, float x1, uint32_t& lo) {
    __half2 h = __floats2half2_rn(x0, x1);
    float2 hf = __half22float2(h);
    __half2 l = __floats2half2_rn(x0 - hf.x, x1 - hf.y);
    lo = *reinterpret_cast<uint32_t*>(&l);
    return *reinterpret_cast<uint32_t*>(&h);
}
__device__ __forceinline__ void unpack_bf2(uint32_t p, float& x0, float& x1) {
    x0 = __uint_as_float(p << 16);
    x1 = __uint_as_float(p & 0xFFFF0000u);
}

// ---------------- kernel 0: tables + W fp16 (full-width parallel) ----------------
__global__ void prep_kernel(const float* __restrict__ WQ,
                            const float* __restrict__ WK,
                            const float* __restrict__ WV) {
    int idx = blockIdx.x * blockDim.x + threadIdx.x;
    if (idx < 4096) {
        float d = fabsf((float)(idx - 2048));
        tDec[idx] = exp2f(log2f(0.96875f) * d);
    }
    if (idx < SEQ * 32) {
        int t = idx >> 5;
        int m = idx & 31;
        float sv = (2.0f * (float)m + 0.4f * (float)HD) / (1.4f * (float)HD);
        float p = ((float)t * (1.0f / 512.0f)) * log2f(sv);
        float s = exp2f(p);
        float rs = exp2f(-p);
        float invf = 1.0f / powf(10000.0f, (float)m / 32.0f);
        float sn, cs;
        sincosf((float)t * invf, &sn, &cs);
        tQc[idx] = cs * s;
        tQs[idx] = sn * s;
        tKc[idx] = cs * rs;
        tKs[idx] = sn * rs;
    }
    if (idx < 3 * HID * HD) {
        int region = idx >> 15;
        int k = (idx & 32767) >> 6;
        int d = idx & 63;
        const float* W = (region == 0) ? WQ : ((region == 1) ? WK : WV);
        __half hw = __float2half_rn(W[k * HD + d]);
        gWf[(region * 64 + d) * HID + k] = *reinterpret_cast<uint16_t*>(&hw);
    }
}

// ---------------- kernel 1: QKV projection, fp16 2-term HMMA + xPos ----------------
// 128 CTAs x 512 thr (16 warps 4x4). CTA tile 128x192, warp tile 32x48.
#define PSTR 72
#define P_WB(s) ((s) * 27648)     // fp16 W stage, 192 x 64 (stride 72)
#define P_AH 55296
#define P_AL 73728
#define P_TOTAL 92160

__global__ __launch_bounds__(512, 1) void proj_kernel(const float* __restrict__ X) {
    extern __shared__ char sm[];
    uint16_t* Ah = (uint16_t*)(sm + P_AH);
    uint16_t* Al = (uint16_t*)(sm + P_AL);
    uint32_t smb = smem_u32(sm);

    int tid = threadIdx.x;
    int wid = tid >> 5, lane = tid & 31;
    int wm = wid >> 2, wn = wid & 3;
    int g = lane >> 2, tc = lane & 3;

    int arow = lane & 15;
    int acolb = (lane >> 4) * 16;
    int krow = (lane & 7) + ((lane >> 4) << 3);
    int kcolb = ((lane >> 3) & 1) * 16;

    const float* Xb = X + (size_t)blockIdx.x * 128 * HID;

    float acc[2][6][4];
#pragma unroll
    for (int mt = 0; mt < 2; mt++)
#pragma unroll
        for (int nt = 0; nt < 6; nt++)
#pragma unroll
            for (int i = 0; i < 4; i++) acc[mt][nt][i] = 0.0f;

    // X for chunk 0 into registers
    float4 xr[4];
#pragma unroll
    for (int it = 0; it < 4; it++) {
        int e = tid + it * 512;
        int r = e >> 4, c = e & 15;
        xr[it] = *(const float4*)&Xb[r * HID + c * 4];
    }
    // W chunk 0 via cp.async
#pragma unroll
    for (int it = 0; it < 3; it++) {
        int e = tid + it * 512;
        int r = e >> 3, c = e & 7;
        CPA16(smb + P_WB(0) + r * 144 + c * 16, &gWf[r * HID + c * 8]);
    }
    CPA_COMMIT();

    for (int chunk = 0; chunk < 8; chunk++) {
        int s = chunk & 1;
        int k0n = (chunk + 1) * 64;
        if (chunk < 7) {
#pragma unroll
            for (int it = 0; it < 3; it++) {
                int e = tid + it * 512;
                int r = e >> 3, c = e & 7;
                CPA16(smb + P_WB(s ^ 1) + r * 144 + c * 16, &gWf[r * HID + k0n + c * 8]);
            }
            CPA_COMMIT();
        }
        // convert register X -> Ah/Al (fp16 hi/lo)
#pragma unroll
        for (int it = 0; it < 4; it++) {
            int e = tid + it * 512;
            int r = e >> 4, c = e & 15;
            float4 v = xr[it];
            uint32_t lo0, lo1;
            uint32_t h0 = splitf16(v.x, v.y, lo0);
            uint32_t h1 = splitf16(v.z, v.w, lo1);
            *(uint2*)&Ah[r * PSTR + 4 * c] = make_uint2(h0, h1);
            *(uint2*)&Al[r * PSTR + 4 * c] = make_uint2(lo0, lo1);
        }
        // issue X loads for next chunk
        if (chunk < 7) {
#pragma unroll
            for (int it = 0; it < 4; it++) {
                int e = tid + it * 512;
                int r = e >> 4, c = e & 15;
                xr[it] = *(const float4*)&Xb[r * HID + k0n + c * 4];
            }
        }
        if (chunk < 7) { CPA_WAIT1(); } else { CPA_WAIT0(); }
        __syncthreads();

        uint32_t wbase = smb + P_WB(s);
#pragma unroll
        for (int ks = 0; ks < 4; ks++) {
            uint32_t ah[2][4], al[2][4];
#pragma unroll
            for (int mt = 0; mt < 2; mt++) {
                uint32_t rb = (uint32_t)((wm * 32 + mt * 16 + arow) * (PSTR * 2) + ks * 32 + acolb);
                LDM_X4(ah[mt], smb + P_AH + rb);
                LDM_X4(al[mt], smb + P_AL + rb);
            }
#pragma unroll
            for (int np = 0; np < 3; np++) {
                int n = wn * 48 + np * 16;
                uint32_t bb = (uint32_t)((n + krow) * (PSTR * 2) + ks * 32 + kcolb);
                uint32_t bf[4];
                LDM_X4(bf, wbase + bb);
#pragma unroll
                for (int mt = 0; mt < 2; mt++) {
                    mma_f16(acc[mt][2 * np], ah[mt], &bf[0]);
                    mma_f16(acc[mt][2 * np], al[mt], &bf[0]);
                    mma_f16(acc[mt][2 * np + 1], ah[mt], &bf[2]);
                    mma_f16(acc[mt][2 * np + 1], al[mt], &bf[2]);
                }
            }
        }
        __syncthreads();
    }

    // epilogue: rotary on Q/K col pairs, split bf16 hi/lo, store
#pragma unroll
    for (int mt = 0; mt < 2; mt++) {
#pragma unroll
        for (int half = 0; half < 2; half++) {
            int lrow = wm * 32 + mt * 16 + g + half * 8;
            int grow = blockIdx.x * 128 + lrow;
            int tpos = grow & (SEQ - 1);
#pragma unroll
            for (int nt = 0; nt < 6; nt++) {
                int c = wn * 48 + nt * 8 + 2 * tc;
                float v0 = acc[mt][nt][half * 2];
                float v1 = acc[mt][nt][half * 2 + 1];
                if (c < 64) {
                    int m = c >> 1;
                    float cs = tQc[tpos * 32 + m], sn = tQs[tpos * 32 + m];
                    float o0 = v0 * cs - v1 * sn;
                    float o1 = v1 * cs + v0 * sn;
                    uint32_t lo;
                    uint32_t hi = split_pair(o0, o1, lo);
                    ((uint32_t*)gQh)[grow * 32 + m] = hi;
                    ((uint32_t*)gQl)[grow * 32 + m] = lo;
                } else if (c < 128) {
                    int m = (c - 64) >> 1;
                    float cs = tKc[tpos * 32 + m], sn = tKs[tpos * 32 + m];
                    float o0 = v0 * cs - v1 * sn;
                    float o1 = v1 * cs + v0 * sn;
                    uint32_t lo;
                    uint32_t hi = split_pair(o0, o1, lo);
                    ((uint32_t*)gKh)[grow * 32 + m] = hi;
                    ((uint32_t*)gKl)[grow * 32 + m] = lo;
                } else {
                    int m = (c - 128) >> 1;
                    uint32_t lo;
                    uint32_t hi = split_pair(v0, v1, lo);
                    ((uint32_t*)gVh)[grow * 32 + m] = hi;
                    ((uint32_t*)gVl)[grow * 32 + m] = lo;
                }
            }
        }
    }
}

// ---------------- kernel 1.5: chunk KV state C_c ----------------
#define SC_KH 0
#define SC_KL 9216
#define SC_VH 18432
#define SC_VL 27648
#define SC_TOTAL 36864

__global__ __launch_bounds__(128) void state_kernel() {
    extern __shared__ char sm[];
    uint32_t smb = smem_u32(sm);
    int c = blockIdx.x, b = blockIdx.y;
    int tid = threadIdx.x;
    int wid = tid >> 5, lane = tid & 31;
    int g = lane >> 2, tc = lane & 3;

    int arow = lane & 15;
    int acolb = (lane >> 4) * 16;
    int krow = (lane & 7) + ((lane >> 4) << 3);
    int kcolb = ((lane >> 3) & 1) * 16;

    float acc[8][4];
#pragma unroll
    for (int nd = 0; nd < 8; nd++)
#pragma unroll
        for (int i = 0; i < 4; i++) acc[nd][i] = 0.0f;

    for (int jt = 0; jt < 4; jt++) {
        __syncthreads();
        int jb = b * SEQ + c * 256 + jt * 64;
#pragma unroll
        for (int it = 0; it < 4; it++) {
            int e = tid + it * 128;
            int r = e >> 3, cc = e & 7;
            *(float4*)(sm + SC_KH + r * 144 + cc * 16) = *(const float4*)&gKh[(size_t)(jb + r) * HD + cc * 8];
            *(float4*)(sm + SC_KL + r * 144 + cc * 16) = *(const float4*)&gKl[(size_t)(jb + r) * HD + cc * 8];
        }
#pragma unroll
        for (int it = 0; it < 16; it++) {
            int p = tid + it * 128;
            int r = p >> 5, vp = p & 31;
            uint32_t hi = ((const uint32_t*)gVh)[(size_t)(jb + r) * 32 + vp];
            uint32_t lo = ((const uint32_t*)gVl)[(size_t)(jb + r) * 32 + vp];
            float h0, h1, l0, l1;
            unpack_bf2(hi, h0, h1);
            unpack_bf2(lo, l0, l1);
            float w = tDec[2304 - (jt * 64 + r)];
            uint32_t olo;
            uint32_t ohi = split_pair(w * (h0 + l0), w * (h1 + l1), olo);
            *(uint32_t*)(sm + SC_VH + r * 144 + vp * 4) = ohi;
            *(uint32_t*)(sm + SC_VL + r * 144 + vp * 4) = olo;
        }
        __syncthreads();

#pragma unroll
        for (int ks = 0; ks < 4; ks++) {
            uint32_t ab = (uint32_t)((ks * 16 + krow) * 144 + wid * 32 + kcolb);
            uint32_t ah[4], al[4];
            LDM_X4T(ah, smb + SC_KH + ab);
            LDM_X4T(al, smb + SC_KL + ab);
#pragma unroll
            for (int ndp = 0; ndp < 4; ndp++) {
                uint32_t vb = (uint32_t)((ks * 16 + arow) * 144 + ndp * 32 + acolb);
                uint32_t vh[4], vl[4];
                LDM_X4T(vh, smb + SC_VH + vb);
                LDM_X4T(vl, smb + SC_VL + vb);
                mma_bf16(acc[2 * ndp], ah, &vh[0]);
                mma_bf16(acc[2 * ndp], ah, &vl[0]);
                mma_bf16(acc[2 * ndp], al, &vh[0]);
                mma_bf16(acc[2 * ndp + 1], ah, &vh[2]);
                mma_bf16(acc[2 * ndp + 1], ah, &vl[2]);
                mma_bf16(acc[2 * ndp + 1], al, &vh[2]);
            }
        }
    }

    float* Cb = gC + ((size_t)(b * 8 + c)) * 4096;
#pragma unroll
    for (int nd = 0; nd < 8; nd++) {
        int v = nd * 8 + 2 * tc;
        int d0 = wid * 16 + g;
        *(float2*)&Cb[d0 * 64 + v] = make_float2(acc[nd][0], acc[nd][1]);
        *(float2*)&Cb[(d0 + 8) * 64 + v] = make_float2(acc[nd][2], acc[nd][3]);
    }
}

// ---------------- kernel 2: retention attention (128-row CTA, one wave) ----------------
// grid (16, 8) x 256 thr (8 warps). Warp = 16 q-rows x full 64; warps 0-3 qtile lo, 4-7 hi.
#define ASTR 72
#define A_QH 0
#define A_QL 18432
#define A_MH 36864
#define A_ML 46080
#define A_ST 55296
#define A_STSZ 36864
#define A_DEC (A_ST + 2 * A_STSZ)            // 129024: decay window 511 floats
#define A_TOTAL (A_DEC + 2048)               // 131072

__device__ __forceinline__ void attn_prefetch(uint32_t smb, int st, int kb, int tid) {
    uint32_t base = smb + A_ST + st * A_STSZ;
#pragma unroll
    for (int it = 0; it < 2; it++) {
        int e = tid + it * 256;
        int r = e >> 3, c = e & 7;
        uint32_t off = (uint32_t)(r * 144 + c * 16);
        CPA16(base + off, &gKh[(size_t)(kb + r) * HD + c * 8]);
        CPA16(base + 9216 + off, &gKl[(size_t)(kb + r) * HD + c * 8]);
        CPA16(base + 18432 + off, &gVh[(size_t)(kb + r) * HD + c * 8]);
        CPA16(base + 27648 + off, &gVl[(size_t)(kb + r) * HD + c * 8]);
    }
}

__global__ __launch_bounds__(256) void attn_kernel(float* __restrict__ out) {
    extern __shared__ char sm[];
    uint16_t* Qh = (uint16_t*)(sm + A_QH);
    uint16_t* Ql = (uint16_t*)(sm + A_QL);
    float* sDec = (float*)(sm + A_DEC);
    uint32_t smb = smem_u32(sm);

    int qtp = blockIdx.x, b = blockIdx.y;
    int tid = threadIdx.x;
    int wid = tid >> 5, lane = tid & 31;
    int qsub = wid >> 2, wq = wid & 3;
    int g = lane >> 2, tc = lane & 3;
    int q0 = qtp * 128;
    int gb = b * SEQ + q0;
    int chunk = qtp >> 1;
    int c4t = chunk * 4;
    int qt_w = qtp * 2 + qsub;

    int arow = lane & 15;
    int acolb = (lane >> 4) * 16;
    int krow = (lane & 7) + ((lane >> 4) << 3);
    int kcolb = ((lane >> 3) & 1) * 16;

    // prefetch tile 0
    attn_prefetch(smb, 0, b * SEQ + c4t * 64, tid);
    CPA_COMMIT();

    // load Q (128 rows, hi/lo), decay window, state M
#pragma unroll
    for (int it = 0; it < 4; it++) {
        int e = tid + it * 256;
        int r = e >> 3, c = e & 7;
        *(float4*)&Qh[r * ASTR + c * 8] = *(const float4*)&gQh[(gb + r) * HD + c * 8];
        *(float4*)&Ql[r * ASTR + c * 8] = *(const float4*)&gQl[(gb + r) * HD + c * 8];
    }
    for (int d = tid; d < 511; d += 256) sDec[d] = tDec[d + 1793];
    if (chunk >= 1) {
        const float2* C1 = (const float2*)(gC + ((size_t)(b * 8 + chunk - 1)) * 4096);
        const float2* C2 = (chunk >= 2) ? (const float2*)(gC + ((size_t)(b * 8 + chunk - 2)) * 4096) : (const float2*)0;
        const float G256 = 2.952517e-4f;   // gamma^256
#pragma unroll
        for (int it = 0; it < 8; it++) {
            int p = tid + it * 256;
            int d = p >> 5, vp = p & 31;
            float2 v = C1[p];
            if (C2) {
                float2 w = C2[p];
                v.x += G256 * w.x;
                v.y += G256 * w.y;
            }
            uint32_t lo;
            uint32_t hi = split_pair(v.x, v.y, lo);
            *(uint32_t*)(sm + A_MH + d * 144 + vp * 4) = hi;
            *(uint32_t*)(sm + A_ML + d * 144 + vp * 4) = lo;
        }
    }
    __syncthreads();

    // preload Q fragments (per-warp rows)
    uint32_t qh[4][4], ql[4][4];
#pragma unroll
    for (int ks = 0; ks < 4; ks++) {
        uint32_t rb = (uint32_t)((qsub * 64 + wq * 16 + arow) * (ASTR * 2) + ks * 32 + acolb);
        LDM_X4(qh[ks], smb + A_QH + rb);
        LDM_X4(ql[ks], smb + A_QL + rb);
    }

    float oa[8][4];
#pragma unroll
    for (int nd = 0; nd < 8; nd++)
#pragma unroll
        for (int i = 0; i < 4; i++) oa[nd][i] = 0.0f;

    int i0 = q0 + qsub * 64 + wq * 16 + g;

    // ---- state apply ----
    if (chunk >= 1) {
        float T[8][4];
#pragma unroll
        for (int nd = 0; nd < 8; nd++)
#pragma unroll
            for (int i = 0; i < 4; i++) T[nd][i] = 0.0f;
#pragma unroll
        for (int ks = 0; ks < 4; ks++) {
#pragma unroll
            for (int ndp = 0; ndp < 4; ndp++) {
                uint32_t vb = (uint32_t)((ks * 16 + arow) * 144 + ndp * 32 + acolb);
                uint32_t mh[4], ml[4];
                LDM_X4T(mh, smb + A_MH + vb);
                LDM_X4T(ml, smb + A_ML + vb);
                mma_bf16(T[2 * ndp], qh[ks], &mh[0]);
                mma_bf16(T[2 * ndp], qh[ks], &ml[0]);
                mma_bf16(T[2 * ndp], ql[ks], &mh[0]);
                mma_bf16(T[2 * ndp + 1], qh[ks], &mh[2]);
                mma_bf16(T[2 * ndp + 1], qh[ks], &ml[2]);
                mma_bf16(T[2 * ndp + 1], ql[ks], &mh[2]);
            }
        }
        int c0 = chunk * 256;
        float sc0 = sDec[i0 - c0 + 255];
        float sc1 = sDec[i0 + 8 - c0 + 255];
#pragma unroll
        for (int nd = 0; nd < 8; nd++) {
            oa[nd][0] += sc0 * T[nd][0];
            oa[nd][1] += sc0 * T[nd][1];
            oa[nd][2] += sc1 * T[nd][2];
            oa[nd][3] += sc1 * T[nd][3];
        }
    }

    // ---- 4 intra-chunk tiles ----
    for (int i = 0; i < 4; i++) {
        int kt = c4t + i;
        int s = i & 1;
        int dd = qt_w - kt;
        bool nr = (dd <= 2) && (dd >= -2);
        if (i < 3) {
            attn_prefetch(smb, s ^ 1, b * SEQ + (kt + 1) * 64, tid);
            CPA_COMMIT();
            CPA_WAIT1();
        } else {
            CPA_WAIT0();
        }
        __syncthreads();

        uint32_t stb = smb + A_ST + s * A_STSZ;
        uint32_t khB = stb, klB = stb + 9216, vhB = stb + 18432, vlB = stb + 27648;

        float sreg[8][4];
#pragma unroll
        for (int nt = 0; nt < 8; nt++)
#pragma unroll
            for (int ii = 0; ii < 4; ii++) sreg[nt][ii] = 0.0f;

        if (nr) {
#pragma unroll
            for (int ks = 0; ks < 4; ks++) {
#pragma unroll
                for (int np = 0; np < 4; np++) {
                    uint32_t bb = (uint32_t)((np * 16 + krow) * (ASTR * 2) + ks * 32 + kcolb);
                    uint32_t kh[4], kl[4];
                    LDM_X4(kh, khB + bb);
                    LDM_X4(kl, klB + bb);
                    mma_bf16(sreg[2 * np], qh[ks], &kh[0]);
                    mma_bf16(sreg[2 * np], qh[ks], &kl[0]);
                    mma_bf16(sreg[2 * np], ql[ks], &kh[0]);
                    mma_bf16(sreg[2 * np + 1], qh[ks], &kh[2]);
                    mma_bf16(sreg[2 * np + 1], qh[ks], &kl[2]);
                    mma_bf16(sreg[2 * np + 1], ql[ks], &kh[2]);
                }
            }
#pragma unroll
            for (int nt = 0; nt < 8; nt++) {
                int base = i0 - (kt * 64 + nt * 8 + 2 * tc) + 255;
                sreg[nt][0] *= sDec[base];
                sreg[nt][1] *= sDec[base - 1];
                sreg[nt][2] *= sDec[base + 8];
                sreg[nt][3] *= sDec[base + 7];
            }
#pragma unroll
            for (int ks2 = 0; ks2 < 4; ks2++) {
                float* s0 = sreg[2 * ks2];
                float* s1 = sreg[2 * ks2 + 1];
                uint32_t ah[4], al[4];
                ah[0] = split_pair(s0[0], s0[1], al[0]);
                ah[1] = split_pair(s0[2], s0[3], al[1]);
                ah[2] = split_pair(s1[0], s1[1], al[2]);
                ah[3] = split_pair(s1[2], s1[3], al[3]);
#pragma unroll
                for (int ndp = 0; ndp < 4; ndp++) {
                    uint32_t vb = (uint32_t)((ks2 * 16 + arow) * (ASTR * 2) + ndp * 32 + acolb);
                    uint32_t vh[4], vl[4];
                    LDM_X4T(vh, vhB + vb);
                    LDM_X4T(vl, vlB + vb);
                    mma_bf16(oa[2 * ndp], ah, &vh[0]);
                    mma_bf16(oa[2 * ndp], ah, &vl[0]);
                    mma_bf16(oa[2 * ndp], al, &vh[0]);
                    mma_bf16(oa[2 * ndp + 1], ah, &vh[2]);
                    mma_bf16(oa[2 * ndp + 1], ah, &vl[2]);
                    mma_bf16(oa[2 * ndp + 1], al, &vh[2]);
                }
            }
        } else {
            // far tile (|dd| == 3): decay <= gamma^129 -> 1-term bf16
#pragma unroll
            for (int ks = 0; ks < 4; ks++) {
#pragma unroll
                for (int np = 0; np < 4; np++) {
                    uint32_t bb = (uint32_t)((np * 16 + krow) * (ASTR * 2) + ks * 32 + kcolb);
                    uint32_t kh[4];
                    LDM_X4(kh, khB + bb);
                    mma_bf16(sreg[2 * np], qh[ks], &kh[0]);
                    mma_bf16(sreg[2 * np + 1], qh[ks], &kh[2]);
                }
            }
#pragma unroll
            for (int nt = 0; nt < 8; nt++) {
                int base = i0 - (kt * 64 + nt * 8 + 2 * tc) + 255;
                sreg[nt][0] *= sDec[base];
                sreg[nt][1] *= sDec[base - 1];
                sreg[nt][2] *= sDec[base + 8];
                sreg[nt][3] *= sDec[base + 7];
            }
#pragma unroll
            for (int ks2 = 0; ks2 < 4; ks2++) {
                float* s0 = sreg[2 * ks2];
                float* s1 = sreg[2 * ks2 + 1];
                uint32_t ah[4];
                ah[0] = pack_bf(s0[0], s0[1]);
                ah[1] = pack_bf(s0[2], s0[3]);
                ah[2] = pack_bf(s1[0], s1[1]);
                ah[3] = pack_bf(s1[2], s1[3]);
#pragma unroll
                for (int ndp = 0; ndp < 4; ndp++) {
                    uint32_t vb = (uint32_t)((ks2 * 16 + arow) * (ASTR * 2) + ndp * 32 + acolb);
                    uint32_t vh[4];
                    LDM_X4T(vh, vhB + vb);
                    mma_bf16(oa[2 * ndp], ah, &vh[0]);
                    mma_bf16(oa[2 * ndp + 1], ah, &vh[2]);
                }
            }
        }
        __syncthreads();
    }

    // store O
#pragma unroll
    for (int nd = 0; nd < 8; nd++) {
        int c = nd * 8 + 2 * tc;
        int r0 = qsub * 64 + wq * 16 + g;
        *(float2*)&out[(size_t)(gb + r0) * HD + c] = make_float2(oa[nd][0], oa[nd][1]);
        *(float2*)&out[(size_t)(gb + r0 + 8) * HD + c] = make_float2(oa[nd][2], oa[nd][3]);
    }
}

// ---------------- launch ----------------
extern "C" void kernel_launch(void* const* d_in, const int* in_sizes, int n_in,
                              void* d_out, int out_size) {
    const float* X  = (const float*)d_in[0];
    const float* WQ = (const float*)d_in[1];
    const float* WK = (const float*)d_in[2];
    const float* WV = (const float*)d_in[3];
    float* out = (float*)d_out;

    prep_kernel<<<384, 256>>>(WQ, WK, WV);

    cudaFuncSetAttribute(proj_kernel, cudaFuncAttributeMaxDynamicSharedMemorySize, P_TOTAL);
    proj_kernel<<<128, 512, P_TOTAL>>>(X);

    cudaFuncSetAttribute(state_kernel, cudaFuncAttributeMaxDynamicSharedMemorySize, SC_TOTAL);
    state_kernel<<<dim3(7, B), 128, SC_TOTAL>>>();

    cudaFuncSetAttribute(attn_kernel, cudaFuncAttributeMaxDynamicSharedMemorySize, A_TOTAL);
    attn_kernel<<<dim3(16, B), 256, A_TOTAL>>>(out);
}

// round 9
// speedup vs baseline: 1.5834x; 1.1490x over previous
#include <cuda_runtime.h>
#include <cuda_bf16.h>
#include <cuda_fp16.h>
#include <math.h>
#include <stdint.h>

#define B 8
#define SEQ 2048
#define HID 512
#define HD 64

// ---------------- scratch (device globals; no allocation allowed) ----------------
__device__ __align__(256) uint16_t gQh[B * SEQ * HD], gQl[B * SEQ * HD];  // fp16 hi/lo
__device__ __align__(256) uint16_t gKf[B * SEQ * HD];                     // fp16 single
__device__ __align__(256) uint16_t gVf[B * SEQ * HD];                     // fp16 single
__device__ __align__(256) uint16_t gWf[192 * HID];     // fp16 W, [region*64+d][k]
__device__ __align__(256) float gC[B * 8 * HD * HD];   // chunk KV states, fp32
__device__ float tQc[SEQ * 32], tQs[SEQ * 32], tKc[SEQ * 32], tKs[SEQ * 32];
__device__ float tDec[4096];   // gamma^|d|, index d+2048

// ---------------- helpers ----------------
__device__ __forceinline__ void mma_f16(float* d, const uint32_t* a, const uint32_t* b) {
    asm volatile(
        "mma.sync.aligned.m16n8k16.row.col.f32.f16.f16.f32 "
        "{%0,%1,%2,%3}, {%4,%5,%6,%7}, {%8,%9}, {%0,%1,%2,%3};"
        : "+f"(d[0]), "+f"(d[1]), "+f"(d[2]), "+f"(d[3])
        : "r"(a[0]), "r"(a[1]), "r"(a[2]), "r"(a[3]), "r"(b[0]), "r"(b[1]));
}
#define LDM_X4(R, a) \
    asm volatile("ldmatrix.sync.aligned.m8n8.x4.shared.b16 {%0,%1,%2,%3}, [%4];" \
                 : "=r"((R)[0]), "=r"((R)[1]), "=r"((R)[2]), "=r"((R)[3]) : "r"(a))
#define LDM_X4T(R, a) \
    asm volatile("ldmatrix.sync.aligned.m8n8.x4.trans.shared.b16 {%0,%1,%2,%3}, [%4];" \
                 : "=r"((R)[0]), "=r"((R)[1]), "=r"((R)[2]), "=r"((R)[3]) : "r"(a))
#define CPA16(dst, src) \
    asm volatile("cp.async.ca.shared.global [%0], [%1], 16;" \
                 :: "r"(dst), "l"(__cvta_generic_to_global(src)))
#define CPA_COMMIT() asm volatile("cp.async.commit_group;")
#define CPA_WAIT1() asm volatile("cp.async.wait_group 1;")
#define CPA_WAIT0() asm volatile("cp.async.wait_group 0;")
__device__ __forceinline__ uint32_t smem_u32(const void* p) {
    uint32_t a;
    asm("{ .reg .u64 t; cvta.to.shared.u64 t, %1; cvt.u32.u64 %0, t; }" : "=r"(a) : "l"(p));
    return a;
}
// fp16 pair pack (RN)
__device__ __forceinline__ uint32_t packf16(float x0, float x1) {
    __half2 h = __floats2half2_rn(x0, x1);
    return *reinterpret_cast<uint32_t*>(&h);
}
// fp16 2-term split: hi RN pair, lo = RN(residual); hi+lo ~ 2^-23 rel.
__device__ __forceinline__ uint32_t splitf16(float x0, float x1, uint32_t& lo) {
    __half2 h = __floats2half2_rn(x0, x1);
    float2 hf = __half22float2(h);
    __half2 l = __floats2half2_rn(x0 - hf.x, x1 - hf.y);
    lo = *reinterpret_cast<uint32_t*>(&l);
    return *reinterpret_cast<uint32_t*>(&h);
}

// ---------------- kernel 0: tables + W fp16 ----------------
__global__ void prep_kernel(const float* __restrict__ WQ,
                            const float* __restrict__ WK,
                            const float* __restrict__ WV) {
    int idx = blockIdx.x * blockDim.x + threadIdx.x;
    if (idx < 4096) {
        float d = fabsf((float)(idx - 2048));
        tDec[idx] = exp2f(log2f(0.96875f) * d);
    }
    if (idx < SEQ * 32) {
        int t = idx >> 5;
        int m = idx & 31;
        float sv = (2.0f * (float)m + 0.4f * (float)HD) / (1.4f * (float)HD);
        float p = ((float)t * (1.0f / 512.0f)) * log2f(sv);
        float s = exp2f(p);
        float rs = exp2f(-p);
        float invf = 1.0f / powf(10000.0f, (float)m / 32.0f);
        float sn, cs;
        sincosf((float)t * invf, &sn, &cs);
        tQc[idx] = cs * s;
        tQs[idx] = sn * s;
        tKc[idx] = cs * rs;
        tKs[idx] = sn * rs;
    }
    if (idx < 3 * HID * HD) {
        int region = idx >> 15;
        int k = (idx & 32767) >> 6;
        int d = idx & 63;
        const float* W = (region == 0) ? WQ : ((region == 1) ? WK : WV);
        __half hw = __float2half_rn(W[k * HD + d]);
        gWf[(region * 64 + d) * HID + k] = *reinterpret_cast<uint16_t*>(&hw);
    }
}

// ---------------- kernel 1: QKV projection, fp16 2-term HMMA + xPos ----------------
// 128 CTAs x 512 thr (16 warps 4x4). CTA tile 128x192, warp tile 32x48.
#define PSTR 72
#define P_WB(s) ((s) * 27648)
#define P_AH 55296
#define P_AL 73728
#define P_TOTAL 92160

__global__ __launch_bounds__(512, 1) void proj_kernel(const float* __restrict__ X) {
    extern __shared__ char sm[];
    uint16_t* Ah = (uint16_t*)(sm + P_AH);
    uint16_t* Al = (uint16_t*)(sm + P_AL);
    uint32_t smb = smem_u32(sm);

    int tid = threadIdx.x;
    int wid = tid >> 5, lane = tid & 31;
    int wm = wid >> 2, wn = wid & 3;
    int g = lane >> 2, tc = lane & 3;

    int arow = lane & 15;
    int acolb = (lane >> 4) * 16;
    int krow = (lane & 7) + ((lane >> 4) << 3);
    int kcolb = ((lane >> 3) & 1) * 16;

    const float* Xb = X + (size_t)blockIdx.x * 128 * HID;

    float acc[2][6][4];
#pragma unroll
    for (int mt = 0; mt < 2; mt++)
#pragma unroll
        for (int nt = 0; nt < 6; nt++)
#pragma unroll
            for (int i = 0; i < 4; i++) acc[mt][nt][i] = 0.0f;

    float4 xr[4];
#pragma unroll
    for (int it = 0; it < 4; it++) {
        int e = tid + it * 512;
        int r = e >> 4, c = e & 15;
        xr[it] = *(const float4*)&Xb[r * HID + c * 4];
    }
#pragma unroll
    for (int it = 0; it < 3; it++) {
        int e = tid + it * 512;
        int r = e >> 3, c = e & 7;
        CPA16(smb + P_WB(0) + r * 144 + c * 16, &gWf[r * HID + c * 8]);
    }
    CPA_COMMIT();

    for (int chunk = 0; chunk < 8; chunk++) {
        int s = chunk & 1;
        int k0n = (chunk + 1) * 64;
        if (chunk < 7) {
#pragma unroll
            for (int it = 0; it < 3; it++) {
                int e = tid + it * 512;
                int r = e >> 3, c = e & 7;
                CPA16(smb + P_WB(s ^ 1) + r * 144 + c * 16, &gWf[r * HID + k0n + c * 8]);
            }
            CPA_COMMIT();
        }
#pragma unroll
        for (int it = 0; it < 4; it++) {
            int e = tid + it * 512;
            int r = e >> 4, c = e & 15;
            float4 v = xr[it];
            uint32_t lo0, lo1;
            uint32_t h0 = splitf16(v.x, v.y, lo0);
            uint32_t h1 = splitf16(v.z, v.w, lo1);
            *(uint2*)&Ah[r * PSTR + 4 * c] = make_uint2(h0, h1);
            *(uint2*)&Al[r * PSTR + 4 * c] = make_uint2(lo0, lo1);
        }
        if (chunk < 7) {
#pragma unroll
            for (int it = 0; it < 4; it++) {
                int e = tid + it * 512;
                int r = e >> 4, c = e & 15;
                xr[it] = *(const float4*)&Xb[r * HID + k0n + c * 4];
            }
        }
        if (chunk < 7) { CPA_WAIT1(); } else { CPA_WAIT0(); }
        __syncthreads();

        uint32_t wbase = smb + P_WB(s);
#pragma unroll
        for (int ks = 0; ks < 4; ks++) {
            uint32_t ah[2][4], al[2][4];
#pragma unroll
            for (int mt = 0; mt < 2; mt++) {
                uint32_t rb = (uint32_t)((wm * 32 + mt * 16 + arow) * (PSTR * 2) + ks * 32 + acolb);
                LDM_X4(ah[mt], smb + P_AH + rb);
                LDM_X4(al[mt], smb + P_AL + rb);
            }
#pragma unroll
            for (int np = 0; np < 3; np++) {
                int n = wn * 48 + np * 16;
                uint32_t bb = (uint32_t)((n + krow) * (PSTR * 2) + ks * 32 + kcolb);
                uint32_t bf[4];
                LDM_X4(bf, wbase + bb);
#pragma unroll
                for (int mt = 0; mt < 2; mt++) {
                    mma_f16(acc[mt][2 * np], ah[mt], &bf[0]);
                    mma_f16(acc[mt][2 * np], al[mt], &bf[0]);
                    mma_f16(acc[mt][2 * np + 1], ah[mt], &bf[2]);
                    mma_f16(acc[mt][2 * np + 1], al[mt], &bf[2]);
                }
            }
        }
        __syncthreads();
    }

    // epilogue: rotary, then Q -> fp16 hi/lo, K/V -> fp16 single
#pragma unroll
    for (int mt = 0; mt < 2; mt++) {
#pragma unroll
        for (int half = 0; half < 2; half++) {
            int lrow = wm * 32 + mt * 16 + g + half * 8;
            int grow = blockIdx.x * 128 + lrow;
            int tpos = grow & (SEQ - 1);
#pragma unroll
            for (int nt = 0; nt < 6; nt++) {
                int c = wn * 48 + nt * 8 + 2 * tc;
                float v0 = acc[mt][nt][half * 2];
                float v1 = acc[mt][nt][half * 2 + 1];
                if (c < 64) {
                    int m = c >> 1;
                    float cs = tQc[tpos * 32 + m], sn = tQs[tpos * 32 + m];
                    float o0 = v0 * cs - v1 * sn;
                    float o1 = v1 * cs + v0 * sn;
                    uint32_t lo;
                    uint32_t hi = splitf16(o0, o1, lo);
                    ((uint32_t*)gQh)[grow * 32 + m] = hi;
                    ((uint32_t*)gQl)[grow * 32 + m] = lo;
                } else if (c < 128) {
                    int m = (c - 64) >> 1;
                    float cs = tKc[tpos * 32 + m], sn = tKs[tpos * 32 + m];
                    float o0 = v0 * cs - v1 * sn;
                    float o1 = v1 * cs + v0 * sn;
                    ((uint32_t*)gKf)[grow * 32 + m] = packf16(o0, o1);
                } else {
                    int m = (c - 128) >> 1;
                    ((uint32_t*)gVf)[grow * 32 + m] = packf16(v0, v1);
                }
            }
        }
    }
}

// ---------------- kernel 1.5: chunk KV state C_c (fp16 1-term) ----------------
#define SC_K 0
#define SC_V 9216
#define SC_TOTAL 18432

__global__ __launch_bounds__(128) void state_kernel() {
    extern __shared__ char sm[];
    uint32_t smb = smem_u32(sm);
    int c = blockIdx.x, b = blockIdx.y;
    int tid = threadIdx.x;
    int wid = tid >> 5, lane = tid & 31;
    int g = lane >> 2, tc = lane & 3;

    int arow = lane & 15;
    int acolb = (lane >> 4) * 16;
    int krow = (lane & 7) + ((lane >> 4) << 3);
    int kcolb = ((lane >> 3) & 1) * 16;

    float acc[8][4];
#pragma unroll
    for (int nd = 0; nd < 8; nd++)
#pragma unroll
        for (int i = 0; i < 4; i++) acc[nd][i] = 0.0f;

    for (int jt = 0; jt < 4; jt++) {
        __syncthreads();
        int jb = b * SEQ + c * 256 + jt * 64;
        // K copy (fp16 single)
#pragma unroll
        for (int it = 0; it < 4; it++) {
            int e = tid + it * 128;
            int r = e >> 3, cc = e & 7;
            *(float4*)(sm + SC_K + r * 144 + cc * 16) = *(const float4*)&gKf[(size_t)(jb + r) * HD + cc * 8];
        }
        // V weighted fp16: w = gamma^(256 - jj)
#pragma unroll
        for (int it = 0; it < 16; it++) {
            int p = tid + it * 128;
            int r = p >> 5, vp = p & 31;
            uint32_t u = ((const uint32_t*)gVf)[(size_t)(jb + r) * 32 + vp];
            __half2 hv = *reinterpret_cast<__half2*>(&u);
            float2 f = __half22float2(hv);
            float w = tDec[2304 - (jt * 64 + r)];
            *(uint32_t*)(sm + SC_V + r * 144 + vp * 4) = packf16(w * f.x, w * f.y);
        }
        __syncthreads();

        // acc[d][v] += K^T(d x j) @ Vw(j x v), 1-term fp16
#pragma unroll
        for (int ks = 0; ks < 4; ks++) {
            uint32_t ab = (uint32_t)((ks * 16 + krow) * 144 + wid * 32 + kcolb);
            uint32_t ah[4];
            LDM_X4T(ah, smb + SC_K + ab);
#pragma unroll
            for (int ndp = 0; ndp < 4; ndp++) {
                uint32_t vb = (uint32_t)((ks * 16 + arow) * 144 + ndp * 32 + acolb);
                uint32_t vh[4];
                LDM_X4T(vh, smb + SC_V + vb);
                mma_f16(acc[2 * ndp], ah, &vh[0]);
                mma_f16(acc[2 * ndp + 1], ah, &vh[2]);
            }
        }
    }

    float* Cb = gC + ((size_t)(b * 8 + c)) * 4096;
#pragma unroll
    for (int nd = 0; nd < 8; nd++) {
        int v = nd * 8 + 2 * tc;
        int d0 = wid * 16 + g;
        *(float2*)&Cb[d0 * 64 + v] = make_float2(acc[nd][0], acc[nd][1]);
        *(float2*)&Cb[(d0 + 8) * 64 + v] = make_float2(acc[nd][2], acc[nd][3]);
    }
}

// ---------------- kernel 2: retention attention (fp16, 128-row CTA) ----------------
// grid (16, 8) x 256 thr (8 warps). Warp = 16 q-rows x full 64.
#define ASTR 72
#define A_QH 0
#define A_QL 18432
#define A_MH 36864
#define A_ML 46080
#define A_ST 55296
#define A_STSZ 18432
// within stage: K +0, V +9216
#define A_DEC (A_ST + 2 * A_STSZ)            // 92160: decay window 511 floats
#define A_TOTAL (A_DEC + 2048)               // 94208

__device__ __forceinline__ void attn_prefetch(uint32_t smb, int st, int kb, int tid) {
    uint32_t base = smb + A_ST + st * A_STSZ;
#pragma unroll
    for (int it = 0; it < 2; it++) {
        int e = tid + it * 256;
        int r = e >> 3, c = e & 7;
        uint32_t off = (uint32_t)(r * 144 + c * 16);
        CPA16(base + off, &gKf[(size_t)(kb + r) * HD + c * 8]);
        CPA16(base + 9216 + off, &gVf[(size_t)(kb + r) * HD + c * 8]);
    }
}

__global__ __launch_bounds__(256) void attn_kernel(float* __restrict__ out) {
    extern __shared__ char sm[];
    uint16_t* Qh = (uint16_t*)(sm + A_QH);
    uint16_t* Ql = (uint16_t*)(sm + A_QL);
    float* sDec = (float*)(sm + A_DEC);
    uint32_t smb = smem_u32(sm);

    int qtp = blockIdx.x, b = blockIdx.y;
    int tid = threadIdx.x;
    int wid = tid >> 5, lane = tid & 31;
    int qsub = wid >> 2, wq = wid & 3;
    int g = lane >> 2, tc = lane & 3;
    int q0 = qtp * 128;
    int gb = b * SEQ + q0;
    int chunk = qtp >> 1;
    int c4t = chunk * 4;
    int qt_w = qtp * 2 + qsub;

    int arow = lane & 15;
    int acolb = (lane >> 4) * 16;
    int krow = (lane & 7) + ((lane >> 4) << 3);
    int kcolb = ((lane >> 3) & 1) * 16;

    attn_prefetch(smb, 0, b * SEQ + c4t * 64, tid);
    CPA_COMMIT();

    // load Q (128 rows, fp16 hi/lo), decay window, state M
#pragma unroll
    for (int it = 0; it < 4; it++) {
        int e = tid + it * 256;
        int r = e >> 3, c = e & 7;
        *(float4*)&Qh[r * ASTR + c * 8] = *(const float4*)&gQh[(gb + r) * HD + c * 8];
        *(float4*)&Ql[r * ASTR + c * 8] = *(const float4*)&gQl[(gb + r) * HD + c * 8];
    }
    for (int d = tid; d < 511; d += 256) sDec[d] = tDec[d + 1793];
    if (chunk >= 1) {
        const float2* C1 = (const float2*)(gC + ((size_t)(b * 8 + chunk - 1)) * 4096);
        const float2* C2 = (chunk >= 2) ? (const float2*)(gC + ((size_t)(b * 8 + chunk - 2)) * 4096) : (const float2*)0;
        const float G256 = 2.952517e-4f;   // gamma^256
#pragma unroll
        for (int it = 0; it < 8; it++) {
            int p = tid + it * 256;
            int d = p >> 5, vp = p & 31;
            float2 v = C1[p];
            if (C2) {
                float2 w = C2[p];
                v.x += G256 * w.x;
                v.y += G256 * w.y;
            }
            uint32_t lo;
            uint32_t hi = splitf16(v.x, v.y, lo);
            *(uint32_t*)(sm + A_MH + d * 144 + vp * 4) = hi;
            *(uint32_t*)(sm + A_ML + d * 144 + vp * 4) = lo;
        }
    }
    __syncthreads();

    uint32_t qh[4][4], ql[4][4];
#pragma unroll
    for (int ks = 0; ks < 4; ks++) {
        uint32_t rb = (uint32_t)((qsub * 64 + wq * 16 + arow) * (ASTR * 2) + ks * 32 + acolb);
        LDM_X4(qh[ks], smb + A_QH + rb);
        LDM_X4(ql[ks], smb + A_QL + rb);
    }

    float oa[8][4];
#pragma unroll
    for (int nd = 0; nd < 8; nd++)
#pragma unroll
        for (int i = 0; i < 4; i++) oa[nd][i] = 0.0f;

    int i0 = q0 + qsub * 64 + wq * 16 + g;

    // ---- state apply: O += gamma^(i-c0) * Q @ M (3-term fp16) ----
    if (chunk >= 1) {
        float T[8][4];
#pragma unroll
        for (int nd = 0; nd < 8; nd++)
#pragma unroll
            for (int i = 0; i < 4; i++) T[nd][i] = 0.0f;
#pragma unroll
        for (int ks = 0; ks < 4; ks++) {
#pragma unroll
            for (int ndp = 0; ndp < 4; ndp++) {
                uint32_t vb = (uint32_t)((ks * 16 + arow) * 144 + ndp * 32 + acolb);
                uint32_t mh[4], ml[4];
                LDM_X4T(mh, smb + A_MH + vb);
                LDM_X4T(ml, smb + A_ML + vb);
                mma_f16(T[2 * ndp], qh[ks], &mh[0]);
                mma_f16(T[2 * ndp], qh[ks], &ml[0]);
                mma_f16(T[2 * ndp], ql[ks], &mh[0]);
                mma_f16(T[2 * ndp + 1], qh[ks], &mh[2]);
                mma_f16(T[2 * ndp + 1], qh[ks], &ml[2]);
                mma_f16(T[2 * ndp + 1], ql[ks], &mh[2]);
            }
        }
        int c0 = chunk * 256;
        float sc0 = sDec[i0 - c0 + 255];
        float sc1 = sDec[i0 + 8 - c0 + 255];
#pragma unroll
        for (int nd = 0; nd < 8; nd++) {
            oa[nd][0] += sc0 * T[nd][0];
            oa[nd][1] += sc0 * T[nd][1];
            oa[nd][2] += sc1 * T[nd][2];
            oa[nd][3] += sc1 * T[nd][3];
        }
    }

    // ---- 4 intra-chunk tiles ----
    for (int i = 0; i < 4; i++) {
        int kt = c4t + i;
        int s = i & 1;
        int dd = qt_w - kt;
        bool nr = (dd <= 2) && (dd >= -2);
        if (i < 3) {
            attn_prefetch(smb, s ^ 1, b * SEQ + (kt + 1) * 64, tid);
            CPA_COMMIT();
            CPA_WAIT1();
        } else {
            CPA_WAIT0();
        }
        __syncthreads();

        uint32_t kB = smb + A_ST + s * A_STSZ;
        uint32_t vB = kB + 9216;

        float sreg[8][4];
#pragma unroll
        for (int nt = 0; nt < 8; nt++)
#pragma unroll
            for (int ii = 0; ii < 4; ii++) sreg[nt][ii] = 0.0f;

        if (nr) {
            // ---- S = (Qh+Ql) K, 2 mma per half-block ----
#pragma unroll
            for (int ks = 0; ks < 4; ks++) {
#pragma unroll
                for (int np = 0; np < 4; np++) {
                    uint32_t bb = (uint32_t)((np * 16 + krow) * (ASTR * 2) + ks * 32 + kcolb);
                    uint32_t kh[4];
                    LDM_X4(kh, kB + bb);
                    mma_f16(sreg[2 * np], qh[ks], &kh[0]);
                    mma_f16(sreg[2 * np], ql[ks], &kh[0]);
                    mma_f16(sreg[2 * np + 1], qh[ks], &kh[2]);
                    mma_f16(sreg[2 * np + 1], ql[ks], &kh[2]);
                }
            }
#pragma unroll
            for (int nt = 0; nt < 8; nt++) {
                int base = i0 - (kt * 64 + nt * 8 + 2 * tc) + 255;
                sreg[nt][0] *= sDec[base];
                sreg[nt][1] *= sDec[base - 1];
                sreg[nt][2] *= sDec[base + 8];
                sreg[nt][3] *= sDec[base + 7];
            }
            // ---- O += (Sh+Sl) V ----
#pragma unroll
            for (int ks2 = 0; ks2 < 4; ks2++) {
                float* s0 = sreg[2 * ks2];
                float* s1 = sreg[2 * ks2 + 1];
                uint32_t ah[4], al[4];
                ah[0] = splitf16(s0[0], s0[1], al[0]);
                ah[1] = splitf16(s0[2], s0[3], al[1]);
                ah[2] = splitf16(s1[0], s1[1], al[2]);
                ah[3] = splitf16(s1[2], s1[3], al[3]);
#pragma unroll
                for (int ndp = 0; ndp < 4; ndp++) {
                    uint32_t vb = (uint32_t)((ks2 * 16 + arow) * (ASTR * 2) + ndp * 32 + acolb);
                    uint32_t vh[4];
                    LDM_X4T(vh, vB + vb);
                    mma_f16(oa[2 * ndp], ah, &vh[0]);
                    mma_f16(oa[2 * ndp], al, &vh[0]);
                    mma_f16(oa[2 * ndp + 1], ah, &vh[2]);
                    mma_f16(oa[2 * ndp + 1], al, &vh[2]);
                }
            }
        } else {
            // ---- far tile (|dd| == 3): decay <= gamma^129 -> 1-term ----
#pragma unroll
            for (int ks = 0; ks < 4; ks++) {
#pragma unroll
                for (int np = 0; np < 4; np++) {
                    uint32_t bb = (uint32_t)((np * 16 + krow) * (ASTR * 2) + ks * 32 + kcolb);
                    uint32_t kh[4];
                    LDM_X4(kh, kB + bb);
                    mma_f16(sreg[2 * np], qh[ks], &kh[0]);
                    mma_f16(sreg[2 * np + 1], qh[ks], &kh[2]);
                }
            }
#pragma unroll
            for (int nt = 0; nt < 8; nt++) {
                int base = i0 - (kt * 64 + nt * 8 + 2 * tc) + 255;
                sreg[nt][0] *= sDec[base];
                sreg[nt][1] *= sDec[base - 1];
                sreg[nt][2] *= sDec[base + 8];
                sreg[nt][3] *= sDec[base + 7];
            }
#pragma unroll
            for (int ks2 = 0; ks2 < 4; ks2++) {
                float* s0 = sreg[2 * ks2];
                float* s1 = sreg[2 * ks2 + 1];
                uint32_t ah[4];
                ah[0] = packf16(s0[0], s0[1]);
                ah[1] = packf16(s0[2], s0[3]);
                ah[2] = packf16(s1[0], s1[1]);
                ah[3] = packf16(s1[2], s1[3]);
#pragma unroll
                for (int ndp = 0; ndp < 4; ndp++) {
                    uint32_t vb = (uint32_t)((ks2 * 16 + arow) * (ASTR * 2) + ndp * 32 + acolb);
                    uint32_t vh[4];
                    LDM_X4T(vh, vB + vb);
                    mma_f16(oa[2 * ndp], ah, &vh[0]);
                    mma_f16(oa[2 * ndp + 1], ah, &vh[2]);
                }
            }
        }
        __syncthreads();
    }

    // store O
#pragma unroll
    for (int nd = 0; nd < 8; nd++) {
        int c = nd * 8 + 2 * tc;
        int r0 = qsub * 64 + wq * 16 + g;
        *(float2*)&out[(size_t)(gb + r0) * HD + c] = make_float2(oa[nd][0], oa[nd][1]);
        *(float2*)&out[(size_t)(gb + r0 + 8) * HD + c] = make_float2(oa[nd][2], oa[nd][3]);
    }
}

// ---------------- launch ----------------
extern "C" void kernel_launch(void* const* d_in, const int* in_sizes, int n_in,
                              void* d_out, int out_size) {
    const float* X  = (const float*)d_in[0];
    const float* WQ = (const float*)d_in[1];
    const float* WK = (const float*)d_in[2];
    const float* WV = (const float*)d_in[3];
    float* out = (float*)d_out;

    prep_kernel<<<384, 256>>>(WQ, WK, WV);

    cudaFuncSetAttribute(proj_kernel, cudaFuncAttributeMaxDynamicSharedMemorySize, P_TOTAL);
    proj_kernel<<<128, 512, P_TOTAL>>>(X);

    cudaFuncSetAttribute(state_kernel, cudaFuncAttributeMaxDynamicSharedMemorySize, SC_TOTAL);
    state_kernel<<<dim3(7, B), 128, SC_TOTAL>>>();

    cudaFuncSetAttribute(attn_kernel, cudaFuncAttributeMaxDynamicSharedMemorySize, A_TOTAL);
    attn_kernel<<<dim3(16, B), 256, A_TOTAL>>>(out);
}

// round 10
// speedup vs baseline: 1.8406x; 1.1625x over previous
#include <cuda_runtime.h>
#include <cuda_bf16.h>
#include <cuda_fp16.h>
#include <math.h>
#include <stdint.h>

#define B 8
#define SEQ 2048
#define HID 512
#define HD 64

// ---------------- scratch (device globals; no allocation allowed) ----------------
__device__ __align__(256) uint16_t gQh[B * SEQ * HD], gQl[B * SEQ * HD];  // fp16 hi/lo
__device__ __align__(256) uint16_t gKf[B * SEQ * HD];                     // fp16 single
__device__ __align__(256) uint16_t gVf[B * SEQ * HD];                     // fp16 single
__device__ __align__(256) uint16_t gWf[192 * HID];     // fp16 W, [region*64+d][k]
__device__ __align__(256) float gC[B * 8 * HD * HD];   // chunk KV states, fp32
__device__ float tQc[SEQ * 32], tQs[SEQ * 32], tKc[SEQ * 32], tKs[SEQ * 32];
__device__ float tDec[4096];   // gamma^|d|, index d+2048

// ---------------- helpers ----------------
__device__ __forceinline__ void mma_f16(float* d, const uint32_t* a, const uint32_t* b) {
    asm volatile(
        "mma.sync.aligned.m16n8k16.row.col.f32.f16.f16.f32 "
        "{%0,%1,%2,%3}, {%4,%5,%6,%7}, {%8,%9}, {%0,%1,%2,%3};"
        : "+f"(d[0]), "+f"(d[1]), "+f"(d[2]), "+f"(d[3])
        : "r"(a[0]), "r"(a[1]), "r"(a[2]), "r"(a[3]), "r"(b[0]), "r"(b[1]));
}
#define LDM_X4(R, a) \
    asm volatile("ldmatrix.sync.aligned.m8n8.x4.shared.b16 {%0,%1,%2,%3}, [%4];" \
                 : "=r"((R)[0]), "=r"((R)[1]), "=r"((R)[2]), "=r"((R)[3]) : "r"(a))
#define LDM_X4T(R, a) \
    asm volatile("ldmatrix.sync.aligned.m8n8.x4.trans.shared.b16 {%0,%1,%2,%3}, [%4];" \
                 : "=r"((R)[0]), "=r"((R)[1]), "=r"((R)[2]), "=r"((R)[3]) : "r"(a))
#define CPA16(dst, src) \
    asm volatile("cp.async.ca.shared.global [%0], [%1], 16;" \
                 :: "r"(dst), "l"(__cvta_generic_to_global(src)))
#define CPA_COMMIT() asm volatile("cp.async.commit_group;")
#define CPA_WAIT1() asm volatile("cp.async.wait_group 1;")
#define CPA_WAIT0() asm volatile("cp.async.wait_group 0;")
__device__ __forceinline__ uint32_t smem_u32(const void* p) {
    uint32_t a;
    asm("{ .reg .u64 t; cvta.to.shared.u64 t, %1; cvt.u32.u64 %0, t; }" : "=r"(a) : "l"(p));
    return a;
}
// fp16 pair pack (RN)
__device__ __forceinline__ uint32_t packf16(float x0, float x1) {
    __half2 h = __floats2half2_rn(x0, x1);
    return *reinterpret_cast<uint32_t*>(&h);
}
// fp16 2-term split: hi RN pair, lo = RN(residual); hi+lo ~ 2^-23 rel.
__device__ __forceinline__ uint32_t splitf16(float x0, float x1, uint32_t& lo) {
    __half2 h = __floats2half2_rn(x0, x1);
    float2 hf = __half22float2(h);
    __half2 l = __floats2half2_rn(x0 - hf.x, x1 - hf.y);
    lo = *reinterpret_cast<uint32_t*>(&l);
    return *reinterpret_cast<uint32_t*>(&h);
}

// ---------------- kernel 0: tables + W fp16 ----------------
__global__ void prep_kernel(const float* __restrict__ WQ,
                            const float* __restrict__ WK,
                            const float* __restrict__ WV) {
    int idx = blockIdx.x * blockDim.x + threadIdx.x;
    if (idx < 4096) {
        float d = fabsf((float)(idx - 2048));
        tDec[idx] = exp2f(log2f(0.96875f) * d);
    }
    if (idx < SEQ * 32) {
        int t = idx >> 5;
        int m = idx & 31;
        float sv = (2.0f * (float)m + 0.4f * (float)HD) / (1.4f * (float)HD);
        float p = ((float)t * (1.0f / 512.0f)) * log2f(sv);
        float s = exp2f(p);
        float rs = exp2f(-p);
        float invf = 1.0f / powf(10000.0f, (float)m / 32.0f);
        float sn, cs;
        sincosf((float)t * invf, &sn, &cs);
        tQc[idx] = cs * s;
        tQs[idx] = sn * s;
        tKc[idx] = cs * rs;
        tKs[idx] = sn * rs;
    }
    if (idx < 3 * HID * HD) {
        int region = idx >> 15;
        int k = (idx & 32767) >> 6;
        int d = idx & 63;
        const float* W = (region == 0) ? WQ : ((region == 1) ? WK : WV);
        __half hw = __float2half_rn(W[k * HD + d]);
        gWf[(region * 64 + d) * HID + k] = *reinterpret_cast<uint16_t*>(&hw);
    }
}

// ---------------- kernel 1: QKV projection, fp16 1-term HMMA + xPos ----------------
// 128 CTAs x 512 thr (16 warps 4x4). CTA tile 128x192, warp tile 32x48.
#define PSTR 72
#define P_WB(s) ((s) * 27648)     // fp16 W stage, 192 x 64 (stride 72)
#define P_AH 55296
#define P_TOTAL 73728

__global__ __launch_bounds__(512, 1) void proj_kernel(const float* __restrict__ X) {
    extern __shared__ char sm[];
    uint16_t* Ah = (uint16_t*)(sm + P_AH);
    uint32_t smb = smem_u32(sm);

    int tid = threadIdx.x;
    int wid = tid >> 5, lane = tid & 31;
    int wm = wid >> 2, wn = wid & 3;
    int g = lane >> 2, tc = lane & 3;

    int arow = lane & 15;
    int acolb = (lane >> 4) * 16;
    int krow = (lane & 7) + ((lane >> 4) << 3);
    int kcolb = ((lane >> 3) & 1) * 16;

    const float* Xb = X + (size_t)blockIdx.x * 128 * HID;

    float acc[2][6][4];
#pragma unroll
    for (int mt = 0; mt < 2; mt++)
#pragma unroll
        for (int nt = 0; nt < 6; nt++)
#pragma unroll
            for (int i = 0; i < 4; i++) acc[mt][nt][i] = 0.0f;

    float4 xr[4];
#pragma unroll
    for (int it = 0; it < 4; it++) {
        int e = tid + it * 512;
        int r = e >> 4, c = e & 15;
        xr[it] = *(const float4*)&Xb[r * HID + c * 4];
    }
#pragma unroll
    for (int it = 0; it < 3; it++) {
        int e = tid + it * 512;
        int r = e >> 3, c = e & 7;
        CPA16(smb + P_WB(0) + r * 144 + c * 16, &gWf[r * HID + c * 8]);
    }
    CPA_COMMIT();

    for (int chunk = 0; chunk < 8; chunk++) {
        int s = chunk & 1;
        int k0n = (chunk + 1) * 64;
        if (chunk < 7) {
#pragma unroll
            for (int it = 0; it < 3; it++) {
                int e = tid + it * 512;
                int r = e >> 3, c = e & 7;
                CPA16(smb + P_WB(s ^ 1) + r * 144 + c * 16, &gWf[r * HID + k0n + c * 8]);
            }
            CPA_COMMIT();
        }
        // convert register X -> Ah (fp16 single)
#pragma unroll
        for (int it = 0; it < 4; it++) {
            int e = tid + it * 512;
            int r = e >> 4, c = e & 15;
            float4 v = xr[it];
            *(uint2*)&Ah[r * PSTR + 4 * c] =
                make_uint2(packf16(v.x, v.y), packf16(v.z, v.w));
        }
        if (chunk < 7) {
#pragma unroll
            for (int it = 0; it < 4; it++) {
                int e = tid + it * 512;
                int r = e >> 4, c = e & 15;
                xr[it] = *(const float4*)&Xb[r * HID + k0n + c * 4];
            }
        }
        if (chunk < 7) { CPA_WAIT1(); } else { CPA_WAIT0(); }
        __syncthreads();

        uint32_t wbase = smb + P_WB(s);
#pragma unroll
        for (int ks = 0; ks < 4; ks++) {
            uint32_t ah[2][4];
#pragma unroll
            for (int mt = 0; mt < 2; mt++) {
                uint32_t rb = (uint32_t)((wm * 32 + mt * 16 + arow) * (PSTR * 2) + ks * 32 + acolb);
                LDM_X4(ah[mt], smb + P_AH + rb);
            }
#pragma unroll
            for (int np = 0; np < 3; np++) {
                int n = wn * 48 + np * 16;
                uint32_t bb = (uint32_t)((n + krow) * (PSTR * 2) + ks * 32 + kcolb);
                uint32_t bf[4];
                LDM_X4(bf, wbase + bb);
#pragma unroll
                for (int mt = 0; mt < 2; mt++) {
                    mma_f16(acc[mt][2 * np], ah[mt], &bf[0]);
                    mma_f16(acc[mt][2 * np + 1], ah[mt], &bf[2]);
                }
            }
        }
        __syncthreads();
    }

    // epilogue: rotary, then Q -> fp16 hi/lo, K/V -> fp16 single
#pragma unroll
    for (int mt = 0; mt < 2; mt++) {
#pragma unroll
        for (int half = 0; half < 2; half++) {
            int lrow = wm * 32 + mt * 16 + g + half * 8;
            int grow = blockIdx.x * 128 + lrow;
            int tpos = grow & (SEQ - 1);
#pragma unroll
            for (int nt = 0; nt < 6; nt++) {
                int c = wn * 48 + nt * 8 + 2 * tc;
                float v0 = acc[mt][nt][half * 2];
                float v1 = acc[mt][nt][half * 2 + 1];
                if (c < 64) {
                    int m = c >> 1;
                    float cs = tQc[tpos * 32 + m], sn = tQs[tpos * 32 + m];
                    float o0 = v0 * cs - v1 * sn;
                    float o1 = v1 * cs + v0 * sn;
                    uint32_t lo;
                    uint32_t hi = splitf16(o0, o1, lo);
                    ((uint32_t*)gQh)[grow * 32 + m] = hi;
                    ((uint32_t*)gQl)[grow * 32 + m] = lo;
                } else if (c < 128) {
                    int m = (c - 64) >> 1;
                    float cs = tKc[tpos * 32 + m], sn = tKs[tpos * 32 + m];
                    float o0 = v0 * cs - v1 * sn;
                    float o1 = v1 * cs + v0 * sn;
                    ((uint32_t*)gKf)[grow * 32 + m] = packf16(o0, o1);
                } else {
                    int m = (c - 128) >> 1;
                    ((uint32_t*)gVf)[grow * 32 + m] = packf16(v0, v1);
                }
            }
        }
    }
}

// ---------------- kernel 1.5: chunk KV state C_c (fp16 1-term) ----------------
#define SC_K 0
#define SC_V 9216
#define SC_TOTAL 18432

__global__ __launch_bounds__(128) void state_kernel() {
    extern __shared__ char sm[];
    uint32_t smb = smem_u32(sm);
    int c = blockIdx.x, b = blockIdx.y;
    int tid = threadIdx.x;
    int wid = tid >> 5, lane = tid & 31;
    int g = lane >> 2, tc = lane & 3;

    int arow = lane & 15;
    int acolb = (lane >> 4) * 16;
    int krow = (lane & 7) + ((lane >> 4) << 3);
    int kcolb = ((lane >> 3) & 1) * 16;

    float acc[8][4];
#pragma unroll
    for (int nd = 0; nd < 8; nd++)
#pragma unroll
        for (int i = 0; i < 4; i++) acc[nd][i] = 0.0f;

    for (int jt = 0; jt < 4; jt++) {
        __syncthreads();
        int jb = b * SEQ + c * 256 + jt * 64;
#pragma unroll
        for (int it = 0; it < 4; it++) {
            int e = tid + it * 128;
            int r = e >> 3, cc = e & 7;
            *(float4*)(sm + SC_K + r * 144 + cc * 16) = *(const float4*)&gKf[(size_t)(jb + r) * HD + cc * 8];
        }
#pragma unroll
        for (int it = 0; it < 16; it++) {
            int p = tid + it * 128;
            int r = p >> 5, vp = p & 31;
            uint32_t u = ((const uint32_t*)gVf)[(size_t)(jb + r) * 32 + vp];
            __half2 hv = *reinterpret_cast<__half2*>(&u);
            float2 f = __half22float2(hv);
            float w = tDec[2304 - (jt * 64 + r)];
            *(uint32_t*)(sm + SC_V + r * 144 + vp * 4) = packf16(w * f.x, w * f.y);
        }
        __syncthreads();

#pragma unroll
        for (int ks = 0; ks < 4; ks++) {
            uint32_t ab = (uint32_t)((ks * 16 + krow) * 144 + wid * 32 + kcolb);
            uint32_t ah[4];
            LDM_X4T(ah, smb + SC_K + ab);
#pragma unroll
            for (int ndp = 0; ndp < 4; ndp++) {
                uint32_t vb = (uint32_t)((ks * 16 + arow) * 144 + ndp * 32 + acolb);
                uint32_t vh[4];
                LDM_X4T(vh, smb + SC_V + vb);
                mma_f16(acc[2 * ndp], ah, &vh[0]);
                mma_f16(acc[2 * ndp + 1], ah, &vh[2]);
            }
        }
    }

    float* Cb = gC + ((size_t)(b * 8 + c)) * 4096;
#pragma unroll
    for (int nd = 0; nd < 8; nd++) {
        int v = nd * 8 + 2 * tc;
        int d0 = wid * 16 + g;
        *(float2*)&Cb[d0 * 64 + v] = make_float2(acc[nd][0], acc[nd][1]);
        *(float2*)&Cb[(d0 + 8) * 64 + v] = make_float2(acc[nd][2], acc[nd][3]);
    }
}

// ---------------- kernel 2: retention attention (fp16, 128-row CTA) ----------------
// grid (16, 8) x 256 thr (8 warps). Warp = 16 q-rows x full 64.
#define ASTR 72
#define A_QH 0
#define A_QL 18432
#define A_MH 36864
#define A_ML 46080
#define A_ST 55296
#define A_STSZ 18432
// within stage: K +0, V +9216
#define A_DEC (A_ST + 2 * A_STSZ)            // 92160: decay window 511 floats
#define A_TOTAL (A_DEC + 2048)               // 94208

__device__ __forceinline__ void attn_prefetch(uint32_t smb, int st, int kb, int tid) {
    uint32_t base = smb + A_ST + st * A_STSZ;
#pragma unroll
    for (int it = 0; it < 2; it++) {
        int e = tid + it * 256;
        int r = e >> 3, c = e & 7;
        uint32_t off = (uint32_t)(r * 144 + c * 16);
        CPA16(base + off, &gKf[(size_t)(kb + r) * HD + c * 8]);
        CPA16(base + 9216 + off, &gVf[(size_t)(kb + r) * HD + c * 8]);
    }
}

__global__ __launch_bounds__(256) void attn_kernel(float* __restrict__ out) {
    extern __shared__ char sm[];
    uint16_t* Qh = (uint16_t*)(sm + A_QH);
    uint16_t* Ql = (uint16_t*)(sm + A_QL);
    float* sDec = (float*)(sm + A_DEC);
    uint32_t smb = smem_u32(sm);

    int qtp = blockIdx.x, b = blockIdx.y;
    int tid = threadIdx.x;
    int wid = tid >> 5, lane = tid & 31;
    int qsub = wid >> 2, wq = wid & 3;
    int g = lane >> 2, tc = lane & 3;
    int q0 = qtp * 128;
    int gb = b * SEQ + q0;
    int chunk = qtp >> 1;
    int c4t = chunk * 4;
    int qt_w = qtp * 2 + qsub;

    int arow = lane & 15;
    int acolb = (lane >> 4) * 16;
    int krow = (lane & 7) + ((lane >> 4) << 3);
    int kcolb = ((lane >> 3) & 1) * 16;

    attn_prefetch(smb, 0, b * SEQ + c4t * 64, tid);
    CPA_COMMIT();

    // load Q (128 rows, fp16 hi/lo), decay window, state M
#pragma unroll
    for (int it = 0; it < 4; it++) {
        int e = tid + it * 256;
        int r = e >> 3, c = e & 7;
        *(float4*)&Qh[r * ASTR + c * 8] = *(const float4*)&gQh[(gb + r) * HD + c * 8];
        *(float4*)&Ql[r * ASTR + c * 8] = *(const float4*)&gQl[(gb + r) * HD + c * 8];
    }
    for (int d = tid; d < 511; d += 256) sDec[d] = tDec[d + 1793];
    if (chunk >= 1) {
        const float2* C1 = (const float2*)(gC + ((size_t)(b * 8 + chunk - 1)) * 4096);
        const float2* C2 = (chunk >= 2) ? (const float2*)(gC + ((size_t)(b * 8 + chunk - 2)) * 4096) : (const float2*)0;
        const float G256 = 2.952517e-4f;   // gamma^256
#pragma unroll
        for (int it = 0; it < 8; it++) {
            int p = tid + it * 256;
            int d = p >> 5, vp = p & 31;
            float2 v = C1[p];
            if (C2) {
                float2 w = C2[p];
                v.x += G256 * w.x;
                v.y += G256 * w.y;
            }
            uint32_t lo;
            uint32_t hi = splitf16(v.x, v.y, lo);
            *(uint32_t*)(sm + A_MH + d * 144 + vp * 4) = hi;
            *(uint32_t*)(sm + A_ML + d * 144 + vp * 4) = lo;
        }
    }
    __syncthreads();

    uint32_t qh[4][4], ql[4][4];
#pragma unroll
    for (int ks = 0; ks < 4; ks++) {
        uint32_t rb = (uint32_t)((qsub * 64 + wq * 16 + arow) * (ASTR * 2) + ks * 32 + acolb);
        LDM_X4(qh[ks], smb + A_QH + rb);
        LDM_X4(ql[ks], smb + A_QL + rb);
    }

    float oa[8][4];
#pragma unroll
    for (int nd = 0; nd < 8; nd++)
#pragma unroll
        for (int i = 0; i < 4; i++) oa[nd][i] = 0.0f;

    int i0 = q0 + qsub * 64 + wq * 16 + g;

    // ---- state apply: O += gamma^(i-c0) * Q @ M (3-term fp16) ----
    if (chunk >= 1) {
        float T[8][4];
#pragma unroll
        for (int nd = 0; nd < 8; nd++)
#pragma unroll
            for (int i = 0; i < 4; i++) T[nd][i] = 0.0f;
#pragma unroll
        for (int ks = 0; ks < 4; ks++) {
#pragma unroll
            for (int ndp = 0; ndp < 4; ndp++) {
                uint32_t vb = (uint32_t)((ks * 16 + arow) * 144 + ndp * 32 + acolb);
                uint32_t mh[4], ml[4];
                LDM_X4T(mh, smb + A_MH + vb);
                LDM_X4T(ml, smb + A_ML + vb);
                mma_f16(T[2 * ndp], qh[ks], &mh[0]);
                mma_f16(T[2 * ndp], qh[ks], &ml[0]);
                mma_f16(T[2 * ndp], ql[ks], &mh[0]);
                mma_f16(T[2 * ndp + 1], qh[ks], &mh[2]);
                mma_f16(T[2 * ndp + 1], qh[ks], &ml[2]);
                mma_f16(T[2 * ndp + 1], ql[ks], &mh[2]);
            }
        }
        int c0 = chunk * 256;
        float sc0 = sDec[i0 - c0 + 255];
        float sc1 = sDec[i0 + 8 - c0 + 255];
#pragma unroll
        for (int nd = 0; nd < 8; nd++) {
            oa[nd][0] += sc0 * T[nd][0];
            oa[nd][1] += sc0 * T[nd][1];
            oa[nd][2] += sc1 * T[nd][2];
            oa[nd][3] += sc1 * T[nd][3];
        }
    }

    // ---- 4 intra-chunk tiles ----
    for (int i = 0; i < 4; i++) {
        int kt = c4t + i;
        int s = i & 1;
        int dd = qt_w - kt;
        bool nr = (dd <= 2) && (dd >= -2);
        if (i < 3) {
            attn_prefetch(smb, s ^ 1, b * SEQ + (kt + 1) * 64, tid);
            CPA_COMMIT();
            CPA_WAIT1();
        } else {
            CPA_WAIT0();
        }
        __syncthreads();

        uint32_t kB = smb + A_ST + s * A_STSZ;
        uint32_t vB = kB + 9216;

        float sreg[8][4];
#pragma unroll
        for (int nt = 0; nt < 8; nt++)
#pragma unroll
            for (int ii = 0; ii < 4; ii++) sreg[nt][ii] = 0.0f;

        if (nr) {
            // ---- S = (Qh+Ql) K ----
#pragma unroll
            for (int ks = 0; ks < 4; ks++) {
#pragma unroll
                for (int np = 0; np < 4; np++) {
                    uint32_t bb = (uint32_t)((np * 16 + krow) * (ASTR * 2) + ks * 32 + kcolb);
                    uint32_t kh[4];
                    LDM_X4(kh, kB + bb);
                    mma_f16(sreg[2 * np], qh[ks], &kh[0]);
                    mma_f16(sreg[2 * np], ql[ks], &kh[0]);
                    mma_f16(sreg[2 * np + 1], qh[ks], &kh[2]);
                    mma_f16(sreg[2 * np + 1], ql[ks], &kh[2]);
                }
            }
#pragma unroll
            for (int nt = 0; nt < 8; nt++) {
                int base = i0 - (kt * 64 + nt * 8 + 2 * tc) + 255;
                sreg[nt][0] *= sDec[base];
                sreg[nt][1] *= sDec[base - 1];
                sreg[nt][2] *= sDec[base + 8];
                sreg[nt][3] *= sDec[base + 7];
            }
            // ---- O += (Sh+Sl) V ----
#pragma unroll
            for (int ks2 = 0; ks2 < 4; ks2++) {
                float* s0 = sreg[2 * ks2];
                float* s1 = sreg[2 * ks2 + 1];
                uint32_t ah[4], al[4];
                ah[0] = splitf16(s0[0], s0[1], al[0]);
                ah[1] = splitf16(s0[2], s0[3], al[1]);
                ah[2] = splitf16(s1[0], s1[1], al[2]);
                ah[3] = splitf16(s1[2], s1[3], al[3]);
#pragma unroll
                for (int ndp = 0; ndp < 4; ndp++) {
                    uint32_t vb = (uint32_t)((ks2 * 16 + arow) * (ASTR * 2) + ndp * 32 + acolb);
                    uint32_t vh[4];
                    LDM_X4T(vh, vB + vb);
                    mma_f16(oa[2 * ndp], ah, &vh[0]);
                    mma_f16(oa[2 * ndp], al, &vh[0]);
                    mma_f16(oa[2 * ndp + 1], ah, &vh[2]);
                    mma_f16(oa[2 * ndp + 1], al, &vh[2]);
                }
            }
        } else {
            // ---- far tile (|dd| == 3): decay <= gamma^129 -> 1-term ----
#pragma unroll
            for (int ks = 0; ks < 4; ks++) {
#pragma unroll
                for (int np = 0; np < 4; np++) {
                    uint32_t bb = (uint32_t)((np * 16 + krow) * (ASTR * 2) + ks * 32 + kcolb);
                    uint32_t kh[4];
                    LDM_X4(kh, kB + bb);
                    mma_f16(sreg[2 * np], qh[ks], &kh[0]);
                    mma_f16(sreg[2 * np + 1], qh[ks], &kh[2]);
                }
            }
#pragma unroll
            for (int nt = 0; nt < 8; nt++) {
                int base = i0 - (kt * 64 + nt * 8 + 2 * tc) + 255;
                sreg[nt][0] *= sDec[base];
                sreg[nt][1] *= sDec[base - 1];
                sreg[nt][2] *= sDec[base + 8];
                sreg[nt][3] *= sDec[base + 7];
            }
#pragma unroll
            for (int ks2 = 0; ks2 < 4; ks2++) {
                float* s0 = sreg[2 * ks2];
                float* s1 = sreg[2 * ks2 + 1];
                uint32_t ah[4];
                ah[0] = packf16(s0[0], s0[1]);
                ah[1] = packf16(s0[2], s0[3]);
                ah[2] = packf16(s1[0], s1[1]);
                ah[3] = packf16(s1[2], s1[3]);
#pragma unroll
                for (int ndp = 0; ndp < 4; ndp++) {
                    uint32_t vb = (uint32_t)((ks2 * 16 + arow) * (ASTR * 2) + ndp * 32 + acolb);
                    uint32_t vh[4];
                    LDM_X4T(vh, vB + vb);
                    mma_f16(oa[2 * ndp], ah, &vh[0]);
                    mma_f16(oa[2 * ndp + 1], ah, &vh[2]);
                }
            }
        }
        __syncthreads();
    }

    // store O
#pragma unroll
    for (int nd = 0; nd < 8; nd++) {
        int c = nd * 8 + 2 * tc;
        int r0 = qsub * 64 + wq * 16 + g;
        *(float2*)&out[(size_t)(gb + r0) * HD + c] = make_float2(oa[nd][0], oa[nd][1]);
        *(float2*)&out[(size_t)(gb + r0 + 8) * HD + c] = make_float2(oa[nd][2], oa[nd][3]);
    }
}

// ---------------- launch ----------------
extern "C" void kernel_launch(void* const* d_in, const int* in_sizes, int n_in,
                              void* d_out, int out_size) {
    const float* X  = (const float*)d_in[0];
    const float* WQ = (const float*)d_in[1];
    const float* WK = (const float*)d_in[2];
    const float* WV = (const float*)d_in[3];
    float* out = (float*)d_out;

    prep_kernel<<<384, 256>>>(WQ, WK, WV);

    cudaFuncSetAttribute(proj_kernel, cudaFuncAttributeMaxDynamicSharedMemorySize, P_TOTAL);
    proj_kernel<<<128, 512, P_TOTAL>>>(X);

    cudaFuncSetAttribute(state_kernel, cudaFuncAttributeMaxDynamicSharedMemorySize, SC_TOTAL);
    state_kernel<<<dim3(7, B), 128, SC_TOTAL>>>();

    cudaFuncSetAttribute(attn_kernel, cudaFuncAttributeMaxDynamicSharedMemorySize, A_TOTAL);
    attn_kernel<<<dim3(16, B), 256, A_TOTAL>>>(out);
}